// round 7
// baseline (speedup 1.0000x reference)
#include <cuda_runtime.h>

// Problem constants
#define I_LEN 2048
#define J_LEN 2048
#define MDIM  1024
#define NHEAD 64     // "head" axis (weights dim1)
#define HD    16     // per-head contracted feature dim (weights dim2)

// combined scale: (1/sqrt(64)) * log2(e)  -- logits kept in log2 domain
#define CSCALE 0.18033688011112042f

typedef unsigned long long u64;

// ---------------- scratch (static device globals; no allocation) ----------------
__device__ float g_wq[I_LEN * MDIM];
__device__ float g_wk[J_LEN * MDIM];
__device__ float g_wv[J_LEN * MDIM];
__device__ float g_vt[J_LEN * MDIM];      // wv * invD (written by stats; idempotent)
__device__ float g_heads[I_LEN * MDIM];
__device__ float g_m[NHEAD * J_LEN];      // column max of log2-scaled logits

// ---------------- packed fp32x2 FMA (Blackwell sm_100+) ----------------
__device__ __forceinline__ u64 ffma2(u64 a, u64 b, u64 c) {
    u64 d;
    asm("fma.rn.f32x2 %0, %1, %2, %3;" : "=l"(d) : "l"(a), "l"(b), "l"(c));
    return d;
}
__device__ __forceinline__ u64 fdup(float x) {
    u64 d;
    asm("mov.b64 %0, {%1, %1};" : "=l"(d) : "f"(x));
    return d;
}
__device__ __forceinline__ float2 funpack(u64 p) {
    float2 r;
    asm("mov.b64 {%0, %1}, %2;" : "=f"(r.x), "=f"(r.y) : "l"(p));
    return r;
}

// ---------------- exp2 on the MUFU pipe ----------------
__device__ __forceinline__ float fexp2(float x) {
    float y;
    asm("ex2.approx.ftz.f32 %0, %1;" : "=f"(y) : "f"(x));
    return y;
}

// ---------------- SGEMM: C[2048x1024] = A[2048xK] @ B[Kx1024], K=1024 ----------------
// 128x64 tile (M x N), BK=16, 256 threads, 8x4 microtile per thread, FFMA2.
// A held in smem pre-duplicated ({a,a} pairs): As[k][2m] = As[k][2m+1] = A[m,k].
// grid per GEMM = (1024/64) x (2048/128) = 16 x 16 = 256 blocks (fills 148 SMs, ~2/SM).
#define GBM 128
#define GBN 64
#define GBK 16
#define GNK (MDIM / GBK)

__device__ __forceinline__ void sgemm_tile(const float* __restrict__ A,
                                           const float* __restrict__ B,
                                           float* __restrict__ C,
                                           int N, int K) {
    __shared__ float As[2][GBK][2 * GBM];   // duplicated pairs: 16KB per buffer
    __shared__ float Bs[2][GBK][GBN];       // 4KB per buffer

    int tid = threadIdx.x;
    int m0 = blockIdx.y * GBM;
    int n0 = blockIdx.x * GBN;

    // A loads: 128 rows x 16 cols = 512 float4; 2 per thread
    int arow = tid >> 1;            // 0..127
    int acol = (tid & 1) * 8;       // 0 or 8
    // B loads: 16 rows x 64 cols = 256 float4; 1 per thread
    int brow = tid >> 4;            // 0..15
    int bcol = (tid & 15) * 4;      // 0..60

    int tx = tid & 15;              // n-group: cols n0 + tx*4 .. +3
    int ty = tid >> 4;              // m-group: rows ty*4+r and 64+ty*4+r

    const float* Aptr = A + (m0 + arow) * K + acol;
    const float* Bptr = B + brow * N + n0 + bcol;

    u64 acc[8][2];
    #pragma unroll
    for (int r = 0; r < 8; r++) { acc[r][0] = 0ull; acc[r][1] = 0ull; }

    float4 av0 = *(const float4*)Aptr;
    float4 av1 = *(const float4*)(Aptr + 4);
    float4 bv  = *(const float4*)Bptr;

    // store tile 0
    *(u64*)&As[0][acol + 0][2 * arow] = fdup(av0.x);
    *(u64*)&As[0][acol + 1][2 * arow] = fdup(av0.y);
    *(u64*)&As[0][acol + 2][2 * arow] = fdup(av0.z);
    *(u64*)&As[0][acol + 3][2 * arow] = fdup(av0.w);
    *(u64*)&As[0][acol + 4][2 * arow] = fdup(av1.x);
    *(u64*)&As[0][acol + 5][2 * arow] = fdup(av1.y);
    *(u64*)&As[0][acol + 6][2 * arow] = fdup(av1.z);
    *(u64*)&As[0][acol + 7][2 * arow] = fdup(av1.w);
    *(float4*)&Bs[0][brow][bcol] = bv;
    __syncthreads();

    for (int t = 0; t < GNK; t++) {
        int buf = t & 1;
        if (t + 1 < GNK) {
            av0 = *(const float4*)(Aptr + (t + 1) * GBK);
            av1 = *(const float4*)(Aptr + (t + 1) * GBK + 4);
            bv  = *(const float4*)(Bptr + (size_t)(t + 1) * GBK * N);
        }

        #pragma unroll
        for (int kk = 0; kk < GBK; kk++) {
            // pair for m-row m lives at float index 2m
            ulonglong2 a01 = *(const ulonglong2*)&As[buf][kk][ty * 8];
            ulonglong2 a23 = *(const ulonglong2*)&As[buf][kk][ty * 8 + 4];
            ulonglong2 a45 = *(const ulonglong2*)&As[buf][kk][128 + ty * 8];
            ulonglong2 a67 = *(const ulonglong2*)&As[buf][kk][128 + ty * 8 + 4];
            ulonglong2 b01 = *(const ulonglong2*)&Bs[buf][kk][tx * 4];

            u64 ar[8] = { a01.x, a01.y, a23.x, a23.y, a45.x, a45.y, a67.x, a67.y };
            #pragma unroll
            for (int r = 0; r < 8; r++) {
                acc[r][0] = ffma2(ar[r], b01.x, acc[r][0]);
                acc[r][1] = ffma2(ar[r], b01.y, acc[r][1]);
            }
        }

        if (t + 1 < GNK) {
            int nb = buf ^ 1;
            *(u64*)&As[nb][acol + 0][2 * arow] = fdup(av0.x);
            *(u64*)&As[nb][acol + 1][2 * arow] = fdup(av0.y);
            *(u64*)&As[nb][acol + 2][2 * arow] = fdup(av0.z);
            *(u64*)&As[nb][acol + 3][2 * arow] = fdup(av0.w);
            *(u64*)&As[nb][acol + 4][2 * arow] = fdup(av1.x);
            *(u64*)&As[nb][acol + 5][2 * arow] = fdup(av1.y);
            *(u64*)&As[nb][acol + 6][2 * arow] = fdup(av1.z);
            *(u64*)&As[nb][acol + 7][2 * arow] = fdup(av1.w);
            *(float4*)&Bs[nb][brow][bcol] = bv;
        }
        __syncthreads();
    }

    #pragma unroll
    for (int r = 0; r < 8; r++) {
        int row = (r < 4) ? (m0 + ty * 4 + r) : (m0 + 64 + ty * 4 + (r - 4));
        float2 c0 = funpack(acc[r][0]);
        float2 c1 = funpack(acc[r][1]);
        *(float4*)&C[row * N + n0 + tx * 4] = make_float4(c0.x, c0.y, c1.x, c1.y);
    }
}

__global__ __launch_bounds__(256) void gemm3_kernel(const float* __restrict__ q,
                                                    const float* __restrict__ qw,
                                                    const float* __restrict__ k,
                                                    const float* __restrict__ kw,
                                                    const float* __restrict__ v,
                                                    const float* __restrict__ vw) {
    const float* A;
    const float* B;
    float* C;
    if (blockIdx.z == 0)      { A = q; B = qw; C = g_wq; }
    else if (blockIdx.z == 1) { A = k; B = kw; C = g_wk; }
    else                      { A = v; B = vw; C = g_wv; }
    sgemm_tile(A, B, C, MDIM, MDIM);
}

__global__ __launch_bounds__(256) void gemm_out_kernel(const float* __restrict__ ow,
                                                       float* __restrict__ out) {
    sgemm_tile(g_heads, ow, out, MDIM, MDIM);
}

// ---------------- pass A: per-(h,j) column stats over i, fused vt = wv/D ----------------
// grid: (J/128, NHEAD), block 128. Thread owns one column j of head h.
__global__ __launch_bounds__(128) void stats_kernel() {
    int h = blockIdx.y;
    int j = blockIdx.x * 128 + threadIdx.x;
    int c0 = h * HD;

    u64 kp[8];     // 16 k-values as 8 pairs
    {
        const ulonglong2* krow = (const ulonglong2*)&g_wk[j * MDIM + c0];
        #pragma unroll
        for (int k = 0; k < 4; k++) {
            ulonglong2 t = krow[k];
            kp[2 * k] = t.x; kp[2 * k + 1] = t.y;
        }
    }

    __shared__ float sq[128][20];   // 80B row stride (16B aligned)

    float m = -1e30f;
    float D = 0.0f;

    for (int i0 = 0; i0 < I_LEN; i0 += 128) {
        __syncthreads();
        {
            int t = threadIdx.x;
            const float* qrow = &g_wq[(i0 + t) * MDIM + c0];
            #pragma unroll
            for (int k = 0; k < 16; k += 4)
                *(float4*)&sq[t][k] = *(const float4*)&qrow[k];
        }
        __syncthreads();

        #pragma unroll 4
        for (int ii = 0; ii < 128; ii++) {
            ulonglong2 q01 = *(const ulonglong2*)&sq[ii][0];
            ulonglong2 q23 = *(const ulonglong2*)&sq[ii][4];
            ulonglong2 q45 = *(const ulonglong2*)&sq[ii][8];
            ulonglong2 q67 = *(const ulonglong2*)&sq[ii][12];
            u64 pA = 0ull, pB = 0ull;        // pA lanes: s0,s1 ; pB lanes: s2,s3
            pA = ffma2(kp[0], q01.x, pA);  pB = ffma2(kp[1], q01.y, pB);
            pA = ffma2(kp[2], q23.x, pA);  pB = ffma2(kp[3], q23.y, pB);
            pA = ffma2(kp[4], q45.x, pA);  pB = ffma2(kp[5], q45.y, pB);
            pA = ffma2(kp[6], q67.x, pA);  pB = ffma2(kp[7], q67.y, pB);
            float2 fa = funpack(pA);
            float2 fb = funpack(pB);
            float s = ((fa.x + fa.y) + (fb.x + fb.y)) * CSCALE;   // log2-domain logit
            // branch-free online update; ex2(0)==1.0 exactly on the common path
            float mn = fmaxf(m, s);
            float e_old = fexp2(m - mn);
            float e_new = fexp2(s - mn);
            D = __fmaf_rn(D, e_old, e_new);
            m = mn;
        }
    }

    float invd = 1.0f / D;
    g_m[h * J_LEN + j] = m;

    // fused vtilde: vt[j,h,:] = wv[j,h,:] * invd
    {
        const float* vr  = &g_wv[j * MDIM + c0];
        float*       vtr = &g_vt[j * MDIM + c0];
        #pragma unroll
        for (int k = 0; k < 16; k += 4) {
            float4 t = *(const float4*)&vr[k];
            t.x *= invd; t.y *= invd; t.z *= invd; t.w *= invd;
            *(float4*)&vtr[k] = t;
        }
    }
}

// ---------------- pass B: heads[i,h,:] = sum_j 2^(s-m) * vt[j,h,:] ----------------
// grid: (I/256, NHEAD), block 128; each thread owns 2 i-rows. FFMA2 everywhere.
__global__ __launch_bounds__(128) void attn_kernel() {
    int h = blockIdx.y;
    int c0 = h * HD;
    int ia = blockIdx.x * 256 + threadIdx.x;
    int ib = ia + 128;

    u64 qa[8], qb[8], aa[8], ab[8];
    {
        const ulonglong2* ra = (const ulonglong2*)&g_wq[ia * MDIM + c0];
        const ulonglong2* rb = (const ulonglong2*)&g_wq[ib * MDIM + c0];
        #pragma unroll
        for (int k = 0; k < 4; k++) {
            ulonglong2 t = ra[k];
            qa[2 * k] = t.x; qa[2 * k + 1] = t.y;
            ulonglong2 u = rb[k];
            qb[2 * k] = u.x; qb[2 * k + 1] = u.y;
        }
    }
    #pragma unroll
    for (int v = 0; v < 8; v++) { aa[v] = 0ull; ab[v] = 0ull; }

    __shared__ float sk[128][20];
    __shared__ float sv[128][20];
    __shared__ float sm[128];

    for (int j0 = 0; j0 < J_LEN; j0 += 128) {
        __syncthreads();
        {
            int t = threadIdx.x;
            const float* krow = &g_wk[(j0 + t) * MDIM + c0];
            const float* vrow = &g_vt[(j0 + t) * MDIM + c0];
            #pragma unroll
            for (int k = 0; k < 16; k += 4) {
                *(float4*)&sk[t][k] = *(const float4*)&krow[k];
                *(float4*)&sv[t][k] = *(const float4*)&vrow[k];
            }
            sm[t] = g_m[h * J_LEN + j0 + t];
        }
        __syncthreads();

        #pragma unroll 2
        for (int jj = 0; jj < 128; jj++) {
            ulonglong2 k01 = *(const ulonglong2*)&sk[jj][0];
            ulonglong2 k23 = *(const ulonglong2*)&sk[jj][4];
            ulonglong2 k45 = *(const ulonglong2*)&sk[jj][8];
            ulonglong2 k67 = *(const ulonglong2*)&sk[jj][12];

            u64 pAa = 0ull, pBa = 0ull, pAb = 0ull, pBb = 0ull;
            pAa = ffma2(k01.x, qa[0], pAa);  pBa = ffma2(k01.y, qa[1], pBa);
            pAb = ffma2(k01.x, qb[0], pAb);  pBb = ffma2(k01.y, qb[1], pBb);
            pAa = ffma2(k23.x, qa[2], pAa);  pBa = ffma2(k23.y, qa[3], pBa);
            pAb = ffma2(k23.x, qb[2], pAb);  pBb = ffma2(k23.y, qb[3], pBb);
            pAa = ffma2(k45.x, qa[4], pAa);  pBa = ffma2(k45.y, qa[5], pBa);
            pAb = ffma2(k45.x, qb[4], pAb);  pBb = ffma2(k45.y, qb[5], pBb);
            pAa = ffma2(k67.x, qa[6], pAa);  pBa = ffma2(k67.y, qa[7], pBa);
            pAb = ffma2(k67.x, qb[6], pAb);  pBb = ffma2(k67.y, qb[7], pBb);

            float2 a1 = funpack(pAa), a2 = funpack(pBa);
            float2 b1 = funpack(pAb), b2 = funpack(pBb);
            float sa = (a1.x + a1.y) + (a2.x + a2.y);   // same tree as stats
            float sb = (b1.x + b1.y) + (b2.x + b2.y);
            float mj = sm[jj];
            float ea = fexp2(__fmaf_rn(sa, CSCALE, -mj));
            float eb = fexp2(__fmaf_rn(sb, CSCALE, -mj));
            u64 ed = fdup(ea);
            u64 fd = fdup(eb);

            ulonglong2 v01 = *(const ulonglong2*)&sv[jj][0];
            ulonglong2 v23 = *(const ulonglong2*)&sv[jj][4];
            ulonglong2 v45 = *(const ulonglong2*)&sv[jj][8];
            ulonglong2 v67 = *(const ulonglong2*)&sv[jj][12];
            u64 vr[8] = { v01.x, v01.y, v23.x, v23.y, v45.x, v45.y, v67.x, v67.y };
            #pragma unroll
            for (int v = 0; v < 8; v++) {
                aa[v] = ffma2(ed, vr[v], aa[v]);
                ab[v] = ffma2(fd, vr[v], ab[v]);
            }
        }
    }

    {
        float* oa = &g_heads[ia * MDIM + c0];
        float* ob = &g_heads[ib * MDIM + c0];
        #pragma unroll
        for (int k = 0; k < 4; k++) {
            float2 p0 = funpack(aa[2 * k]);
            float2 p1 = funpack(aa[2 * k + 1]);
            *(float4*)&oa[4 * k] = make_float4(p0.x, p0.y, p1.x, p1.y);
            float2 r0 = funpack(ab[2 * k]);
            float2 r1 = funpack(ab[2 * k + 1]);
            *(float4*)&ob[4 * k] = make_float4(r0.x, r0.y, r1.x, r1.y);
        }
    }
}

// ---------------- launch ----------------
extern "C" void kernel_launch(void* const* d_in, const int* in_sizes, int n_in,
                              void* d_out, int out_size) {
    (void)in_sizes; (void)n_in; (void)out_size;
    const float* q  = (const float*)d_in[0];
    const float* k  = (const float*)d_in[1];
    const float* v  = (const float*)d_in[2];
    const float* qw = (const float*)d_in[3];
    const float* kw = (const float*)d_in[4];
    const float* vw = (const float*)d_in[5];
    const float* ow = (const float*)d_in[6];
    float* out = (float*)d_out;

    dim3 ggrid3(MDIM / GBN, I_LEN / GBM, 3);
    gemm3_kernel<<<ggrid3, 256>>>(q, qw, k, kw, v, vw);

    stats_kernel<<<dim3(J_LEN / 128, NHEAD), 128>>>();

    attn_kernel<<<dim3(I_LEN / 256, NHEAD), 128>>>();

    gemm_out_kernel<<<dim3(MDIM / GBN, I_LEN / GBM), 256>>>(ow, out);
}

// round 9
// speedup vs baseline: 1.0771x; 1.0771x over previous
#include <cuda_runtime.h>

// Problem constants
#define I_LEN 2048
#define J_LEN 2048
#define MDIM  1024
#define NHEAD 64     // "head" axis (weights dim1)
#define HD    16     // per-head contracted feature dim (weights dim2)

// combined scale: (1/sqrt(64)) * log2(e)  -- logits kept in log2 domain
#define CSCALE 0.18033688011112042f

typedef unsigned long long u64;

// ---------------- scratch (static device globals; no allocation) ----------------
__device__ float g_wq[I_LEN * MDIM];
__device__ float g_wk[J_LEN * MDIM];
__device__ float g_wv[J_LEN * MDIM];
__device__ float g_vt[J_LEN * MDIM];      // wv * invD (written by stats; idempotent)
__device__ float g_heads[I_LEN * MDIM];
__device__ float g_m[NHEAD * J_LEN];      // column max of log2-scaled logits

// ---------------- packed fp32x2 FMA (Blackwell sm_100+) ----------------
__device__ __forceinline__ u64 ffma2(u64 a, u64 b, u64 c) {
    u64 d;
    asm("fma.rn.f32x2 %0, %1, %2, %3;" : "=l"(d) : "l"(a), "l"(b), "l"(c));
    return d;
}
__device__ __forceinline__ u64 fdup(float x) {
    u64 d;
    asm("mov.b64 %0, {%1, %1};" : "=l"(d) : "f"(x));
    return d;
}
__device__ __forceinline__ float2 funpack(u64 p) {
    float2 r;
    asm("mov.b64 {%0, %1}, %2;" : "=f"(r.x), "=f"(r.y) : "l"(p));
    return r;
}

// ---------------- exp2 on the MUFU pipe ----------------
__device__ __forceinline__ float fexp2(float x) {
    float y;
    asm("ex2.approx.ftz.f32 %0, %1;" : "=f"(y) : "f"(x));
    return y;
}

// ---------------- SGEMM: C[2048x1024] = A[2048xK] @ B[Kx1024], K=1024 ----------------
// 128x64 tile (M x N), BK=16, 128 threads, 8x8 microtile per thread.
// A in smem transposed scalar (As[k][m], no duplication); A operand duplicated
// in-register via fdup (ALU pipe). B read as distinct n-pairs for FFMA2.
// Per kk: 4 LDS.128 (16 crossbar cyc) vs 32 FFMA2 (16 FMA SM-cyc) -- balanced.
#define GBM 128
#define GBN 64
#define GBK 16
#define GNK (MDIM / GBK)

__device__ __forceinline__ void sgemm_tile(const float* __restrict__ A,
                                           const float* __restrict__ B,
                                           float* __restrict__ C,
                                           int N, int K) {
    __shared__ float As[2][GBK][GBM];   // transposed: As[k][m], 8KB per buffer
    __shared__ float Bs[2][GBK][GBN];   // 4KB per buffer

    int tid = threadIdx.x;   // 0..127
    int m0 = blockIdx.y * GBM;
    int n0 = blockIdx.x * GBN;

    // A loads: 128 rows x 16 k = 2048 floats; 16 per thread
    //   rows arow and arow+64; k-range ak..ak+7
    int arow = tid >> 1;            // 0..63
    int ak   = (tid & 1) * 8;       // 0 or 8
    // B loads: 16 rows x 64 cols = 1024 floats; 8 per thread (rows brow, brow+8)
    int brow = tid >> 4;            // 0..7
    int bcol = (tid & 15) * 4;      // 0..60

    int tx = tid & 7;               // n-group: cols n0 + tx*8 .. +7
    int ty = tid >> 3;              // m-group: rows m0 + ty*8 .. +7 (0..15)

    const float* Aptr0 = A + (m0 + arow) * K + ak;
    const float* Aptr1 = A + (m0 + 64 + arow) * K + ak;
    const float* Bptr0 = B + brow * N + n0 + bcol;
    const float* Bptr1 = B + (brow + 8) * N + n0 + bcol;

    u64 acc[8][4];
    #pragma unroll
    for (int r = 0; r < 8; r++)
        #pragma unroll
        for (int c = 0; c < 4; c++) acc[r][c] = 0ull;

    float4 a00 = *(const float4*)Aptr0;
    float4 a01 = *(const float4*)(Aptr0 + 4);
    float4 a10 = *(const float4*)Aptr1;
    float4 a11 = *(const float4*)(Aptr1 + 4);
    float4 bv0 = *(const float4*)Bptr0;
    float4 bv1 = *(const float4*)Bptr1;

    // store tile 0 (A transposed scalar)
    As[0][ak + 0][arow] = a00.x;  As[0][ak + 1][arow] = a00.y;
    As[0][ak + 2][arow] = a00.z;  As[0][ak + 3][arow] = a00.w;
    As[0][ak + 4][arow] = a01.x;  As[0][ak + 5][arow] = a01.y;
    As[0][ak + 6][arow] = a01.z;  As[0][ak + 7][arow] = a01.w;
    As[0][ak + 0][arow + 64] = a10.x;  As[0][ak + 1][arow + 64] = a10.y;
    As[0][ak + 2][arow + 64] = a10.z;  As[0][ak + 3][arow + 64] = a10.w;
    As[0][ak + 4][arow + 64] = a11.x;  As[0][ak + 5][arow + 64] = a11.y;
    As[0][ak + 6][arow + 64] = a11.z;  As[0][ak + 7][arow + 64] = a11.w;
    *(float4*)&Bs[0][brow][bcol]     = bv0;
    *(float4*)&Bs[0][brow + 8][bcol] = bv1;
    __syncthreads();

    for (int t = 0; t < GNK; t++) {
        int buf = t & 1;
        if (t + 1 < GNK) {
            a00 = *(const float4*)(Aptr0 + (t + 1) * GBK);
            a01 = *(const float4*)(Aptr0 + (t + 1) * GBK + 4);
            a10 = *(const float4*)(Aptr1 + (t + 1) * GBK);
            a11 = *(const float4*)(Aptr1 + (t + 1) * GBK + 4);
            bv0 = *(const float4*)(Bptr0 + (size_t)(t + 1) * GBK * N);
            bv1 = *(const float4*)(Bptr1 + (size_t)(t + 1) * GBK * N);
        }

        #pragma unroll
        for (int kk = 0; kk < GBK; kk++) {
            float4 af0 = *(const float4*)&As[buf][kk][ty * 8];
            float4 af1 = *(const float4*)&As[buf][kk][ty * 8 + 4];
            ulonglong2 b01 = *(const ulonglong2*)&Bs[buf][kk][tx * 8];
            ulonglong2 b23 = *(const ulonglong2*)&Bs[buf][kk][tx * 8 + 4];

            float am[8] = { af0.x, af0.y, af0.z, af0.w, af1.x, af1.y, af1.z, af1.w };
            #pragma unroll
            for (int r = 0; r < 8; r++) {
                u64 ad = fdup(am[r]);
                acc[r][0] = ffma2(ad, b01.x, acc[r][0]);
                acc[r][1] = ffma2(ad, b01.y, acc[r][1]);
                acc[r][2] = ffma2(ad, b23.x, acc[r][2]);
                acc[r][3] = ffma2(ad, b23.y, acc[r][3]);
            }
        }

        if (t + 1 < GNK) {
            int nb = buf ^ 1;
            As[nb][ak + 0][arow] = a00.x;  As[nb][ak + 1][arow] = a00.y;
            As[nb][ak + 2][arow] = a00.z;  As[nb][ak + 3][arow] = a00.w;
            As[nb][ak + 4][arow] = a01.x;  As[nb][ak + 5][arow] = a01.y;
            As[nb][ak + 6][arow] = a01.z;  As[nb][ak + 7][arow] = a01.w;
            As[nb][ak + 0][arow + 64] = a10.x;  As[nb][ak + 1][arow + 64] = a10.y;
            As[nb][ak + 2][arow + 64] = a10.z;  As[nb][ak + 3][arow + 64] = a10.w;
            As[nb][ak + 4][arow + 64] = a11.x;  As[nb][ak + 5][arow + 64] = a11.y;
            As[nb][ak + 6][arow + 64] = a11.z;  As[nb][ak + 7][arow + 64] = a11.w;
            *(float4*)&Bs[nb][brow][bcol]     = bv0;
            *(float4*)&Bs[nb][brow + 8][bcol] = bv1;
        }
        __syncthreads();
    }

    #pragma unroll
    for (int r = 0; r < 8; r++) {
        int row = m0 + ty * 8 + r;
        float2 c0 = funpack(acc[r][0]);
        float2 c1 = funpack(acc[r][1]);
        float2 c2 = funpack(acc[r][2]);
        float2 c3 = funpack(acc[r][3]);
        *(float4*)&C[row * N + n0 + tx * 8]     = make_float4(c0.x, c0.y, c1.x, c1.y);
        *(float4*)&C[row * N + n0 + tx * 8 + 4] = make_float4(c2.x, c2.y, c3.x, c3.y);
    }
}

__global__ __launch_bounds__(128, 3) void gemm3_kernel(const float* __restrict__ q,
                                                       const float* __restrict__ qw,
                                                       const float* __restrict__ k,
                                                       const float* __restrict__ kw,
                                                       const float* __restrict__ v,
                                                       const float* __restrict__ vw) {
    const float* A;
    const float* B;
    float* C;
    if (blockIdx.z == 0)      { A = q; B = qw; C = g_wq; }
    else if (blockIdx.z == 1) { A = k; B = kw; C = g_wk; }
    else                      { A = v; B = vw; C = g_wv; }
    sgemm_tile(A, B, C, MDIM, MDIM);
}

__global__ __launch_bounds__(128, 3) void gemm_out_kernel(const float* __restrict__ ow,
                                                          float* __restrict__ out) {
    sgemm_tile(g_heads, ow, out, MDIM, MDIM);
}

// ---------------- pass A: per-(h,j) column stats over i, fused vt = wv/D ----------------
// grid: (J/128, NHEAD), block 128. Thread owns one column j of head h.
__global__ __launch_bounds__(128) void stats_kernel() {
    int h = blockIdx.y;
    int j = blockIdx.x * 128 + threadIdx.x;
    int c0 = h * HD;

    u64 kp[8];     // 16 k-values as 8 pairs
    {
        const ulonglong2* krow = (const ulonglong2*)&g_wk[j * MDIM + c0];
        #pragma unroll
        for (int k = 0; k < 4; k++) {
            ulonglong2 t = krow[k];
            kp[2 * k] = t.x; kp[2 * k + 1] = t.y;
        }
    }

    __shared__ float sq[128][20];   // 80B row stride (16B aligned)

    float m = -1e30f;
    float D = 0.0f;

    for (int i0 = 0; i0 < I_LEN; i0 += 128) {
        __syncthreads();
        {
            int t = threadIdx.x;
            const float* qrow = &g_wq[(i0 + t) * MDIM + c0];
            #pragma unroll
            for (int k = 0; k < 16; k += 4)
                *(float4*)&sq[t][k] = *(const float4*)&qrow[k];
        }
        __syncthreads();

        #pragma unroll 4
        for (int ii = 0; ii < 128; ii++) {
            ulonglong2 q01 = *(const ulonglong2*)&sq[ii][0];
            ulonglong2 q23 = *(const ulonglong2*)&sq[ii][4];
            ulonglong2 q45 = *(const ulonglong2*)&sq[ii][8];
            ulonglong2 q67 = *(const ulonglong2*)&sq[ii][12];
            u64 pA = 0ull, pB = 0ull;        // pA lanes: s0,s1 ; pB lanes: s2,s3
            pA = ffma2(kp[0], q01.x, pA);  pB = ffma2(kp[1], q01.y, pB);
            pA = ffma2(kp[2], q23.x, pA);  pB = ffma2(kp[3], q23.y, pB);
            pA = ffma2(kp[4], q45.x, pA);  pB = ffma2(kp[5], q45.y, pB);
            pA = ffma2(kp[6], q67.x, pA);  pB = ffma2(kp[7], q67.y, pB);
            float2 fa = funpack(pA);
            float2 fb = funpack(pB);
            float s = ((fa.x + fa.y) + (fb.x + fb.y)) * CSCALE;   // log2-domain logit
            // branch-free online update; ex2(0)==1.0 exactly on the common path
            float mn = fmaxf(m, s);
            float e_old = fexp2(m - mn);
            float e_new = fexp2(s - mn);
            D = __fmaf_rn(D, e_old, e_new);
            m = mn;
        }
    }

    float invd = 1.0f / D;
    g_m[h * J_LEN + j] = m;

    // fused vtilde: vt[j,h,:] = wv[j,h,:] * invd
    {
        const float* vr  = &g_wv[j * MDIM + c0];
        float*       vtr = &g_vt[j * MDIM + c0];
        #pragma unroll
        for (int k = 0; k < 16; k += 4) {
            float4 t = *(const float4*)&vr[k];
            t.x *= invd; t.y *= invd; t.z *= invd; t.w *= invd;
            *(float4*)&vtr[k] = t;
        }
    }
}

// ---------------- pass B: heads[i,h,:] = sum_j 2^(s-m) * vt[j,h,:] ----------------
// grid: (I/256, NHEAD), block 128; each thread owns 2 i-rows. FFMA2 everywhere.
__global__ __launch_bounds__(128) void attn_kernel() {
    int h = blockIdx.y;
    int c0 = h * HD;
    int ia = blockIdx.x * 256 + threadIdx.x;
    int ib = ia + 128;

    u64 qa[8], qb[8], aa[8], ab[8];
    {
        const ulonglong2* ra = (const ulonglong2*)&g_wq[ia * MDIM + c0];
        const ulonglong2* rb = (const ulonglong2*)&g_wq[ib * MDIM + c0];
        #pragma unroll
        for (int k = 0; k < 4; k++) {
            ulonglong2 t = ra[k];
            qa[2 * k] = t.x; qa[2 * k + 1] = t.y;
            ulonglong2 u = rb[k];
            qb[2 * k] = u.x; qb[2 * k + 1] = u.y;
        }
    }
    #pragma unroll
    for (int v = 0; v < 8; v++) { aa[v] = 0ull; ab[v] = 0ull; }

    __shared__ float sk[128][20];
    __shared__ float sv[128][20];
    __shared__ float sm[128];

    for (int j0 = 0; j0 < J_LEN; j0 += 128) {
        __syncthreads();
        {
            int t = threadIdx.x;
            const float* krow = &g_wk[(j0 + t) * MDIM + c0];
            const float* vrow = &g_vt[(j0 + t) * MDIM + c0];
            #pragma unroll
            for (int k = 0; k < 16; k += 4) {
                *(float4*)&sk[t][k] = *(const float4*)&krow[k];
                *(float4*)&sv[t][k] = *(const float4*)&vrow[k];
            }
            sm[t] = g_m[h * J_LEN + j0 + t];
        }
        __syncthreads();

        #pragma unroll 2
        for (int jj = 0; jj < 128; jj++) {
            ulonglong2 k01 = *(const ulonglong2*)&sk[jj][0];
            ulonglong2 k23 = *(const ulonglong2*)&sk[jj][4];
            ulonglong2 k45 = *(const ulonglong2*)&sk[jj][8];
            ulonglong2 k67 = *(const ulonglong2*)&sk[jj][12];

            u64 pAa = 0ull, pBa = 0ull, pAb = 0ull, pBb = 0ull;
            pAa = ffma2(k01.x, qa[0], pAa);  pBa = ffma2(k01.y, qa[1], pBa);
            pAb = ffma2(k01.x, qb[0], pAb);  pBb = ffma2(k01.y, qb[1], pBb);
            pAa = ffma2(k23.x, qa[2], pAa);  pBa = ffma2(k23.y, qa[3], pBa);
            pAb = ffma2(k23.x, qb[2], pAb);  pBb = ffma2(k23.y, qb[3], pBb);
            pAa = ffma2(k45.x, qa[4], pAa);  pBa = ffma2(k45.y, qa[5], pBa);
            pAb = ffma2(k45.x, qb[4], pAb);  pBb = ffma2(k45.y, qb[5], pBb);
            pAa = ffma2(k67.x, qa[6], pAa);  pBa = ffma2(k67.y, qa[7], pBa);
            pAb = ffma2(k67.x, qb[6], pAb);  pBb = ffma2(k67.y, qb[7], pBb);

            float2 a1 = funpack(pAa), a2 = funpack(pBa);
            float2 b1 = funpack(pAb), b2 = funpack(pBb);
            float sa = (a1.x + a1.y) + (a2.x + a2.y);   // same tree as stats
            float sb = (b1.x + b1.y) + (b2.x + b2.y);
            float mj = sm[jj];
            float ea = fexp2(__fmaf_rn(sa, CSCALE, -mj));
            float eb = fexp2(__fmaf_rn(sb, CSCALE, -mj));
            u64 ed = fdup(ea);
            u64 fd = fdup(eb);

            ulonglong2 v01 = *(const ulonglong2*)&sv[jj][0];
            ulonglong2 v23 = *(const ulonglong2*)&sv[jj][4];
            ulonglong2 v45 = *(const ulonglong2*)&sv[jj][8];
            ulonglong2 v67 = *(const ulonglong2*)&sv[jj][12];
            u64 vr[8] = { v01.x, v01.y, v23.x, v23.y, v45.x, v45.y, v67.x, v67.y };
            #pragma unroll
            for (int v = 0; v < 8; v++) {
                aa[v] = ffma2(ed, vr[v], aa[v]);
                ab[v] = ffma2(fd, vr[v], ab[v]);
            }
        }
    }

    {
        float* oa = &g_heads[ia * MDIM + c0];
        float* ob = &g_heads[ib * MDIM + c0];
        #pragma unroll
        for (int k = 0; k < 4; k++) {
            float2 p0 = funpack(aa[2 * k]);
            float2 p1 = funpack(aa[2 * k + 1]);
            *(float4*)&oa[4 * k] = make_float4(p0.x, p0.y, p1.x, p1.y);
            float2 r0 = funpack(ab[2 * k]);
            float2 r1 = funpack(ab[2 * k + 1]);
            *(float4*)&ob[4 * k] = make_float4(r0.x, r0.y, r1.x, r1.y);
        }
    }
}

// ---------------- launch ----------------
extern "C" void kernel_launch(void* const* d_in, const int* in_sizes, int n_in,
                              void* d_out, int out_size) {
    (void)in_sizes; (void)n_in; (void)out_size;
    const float* q  = (const float*)d_in[0];
    const float* k  = (const float*)d_in[1];
    const float* v  = (const float*)d_in[2];
    const float* qw = (const float*)d_in[3];
    const float* kw = (const float*)d_in[4];
    const float* vw = (const float*)d_in[5];
    const float* ow = (const float*)d_in[6];
    float* out = (float*)d_out;

    dim3 ggrid3(MDIM / GBN, I_LEN / GBM, 3);
    gemm3_kernel<<<ggrid3, 128>>>(q, qw, k, kw, v, vw);

    stats_kernel<<<dim3(J_LEN / 128, NHEAD), 128>>>();

    attn_kernel<<<dim3(I_LEN / 256, NHEAD), 128>>>();

    gemm_out_kernel<<<dim3(MDIM / GBN, I_LEN / GBM), 128>>>(ow, out);
}

// round 10
// speedup vs baseline: 1.1183x; 1.0383x over previous
#include <cuda_runtime.h>

// Problem constants
#define I_LEN 2048
#define J_LEN 2048
#define MDIM  1024
#define NHEAD 64     // "head" axis (weights dim1)
#define HD    16     // per-head contracted feature dim (weights dim2)

// combined scale: (1/sqrt(64)) * log2(e)  -- logits kept in log2 domain
#define CSCALE 0.18033688011112042f

typedef unsigned long long u64;

// ---------------- scratch (static device globals; no allocation) ----------------
__device__ float g_wq[I_LEN * MDIM];
__device__ float g_wk[J_LEN * MDIM];
__device__ float g_wv[J_LEN * MDIM];
__device__ float g_vt[J_LEN * MDIM];      // wv * invD (written by stats; idempotent)
__device__ float g_heads[I_LEN * MDIM];
__device__ float g_m[NHEAD * J_LEN];      // column max of log2-scaled logits

// ---------------- packed fp32x2 FMA (Blackwell sm_100+) ----------------
__device__ __forceinline__ u64 ffma2(u64 a, u64 b, u64 c) {
    u64 d;
    asm("fma.rn.f32x2 %0, %1, %2, %3;" : "=l"(d) : "l"(a), "l"(b), "l"(c));
    return d;
}
__device__ __forceinline__ u64 fdup(float x) {
    u64 d;
    asm("mov.b64 %0, {%1, %1};" : "=l"(d) : "f"(x));
    return d;
}
__device__ __forceinline__ float2 funpack(u64 p) {
    float2 r;
    asm("mov.b64 {%0, %1}, %2;" : "=f"(r.x), "=f"(r.y) : "l"(p));
    return r;
}

// ---------------- exp2 on the MUFU pipe ----------------
__device__ __forceinline__ float fexp2(float x) {
    float y;
    asm("ex2.approx.ftz.f32 %0, %1;" : "=f"(y) : "f"(x));
    return y;
}

// ---------------- SGEMM: C[2048x1024] = A[2048xK] @ B[Kx1024], K=1024 ----------------
// 128x128 tile, BK=16, 128 threads, 16m x 8n microtile per thread.
// Crossbar:FMA per kk per warp = 24 : 128 cyc (ratio 0.75) -> FMA-pipe bound.
// A in smem transposed scalar (As[k][m]); duplicated in-register via fdup
// (MOVs fit in the rt2 issue gaps of the FMA pipe). B read as 4 n-pairs.
#define GBM 128
#define GBN 128
#define GBK 16
#define GNK (MDIM / GBK)

__device__ __forceinline__ void sgemm_tile(const float* __restrict__ A,
                                           const float* __restrict__ B,
                                           float* __restrict__ C,
                                           int N, int K) {
    __shared__ float As[2][GBK][GBM];   // transposed: As[k][m], 8KB per buffer
    __shared__ float Bs[2][GBK][GBN];   // 8KB per buffer

    int tid = threadIdx.x;   // 0..127
    int m0 = blockIdx.y * GBM;
    int n0 = blockIdx.x * GBN;

    // A loads: 128 rows x 16 k = 2048 floats; 16 per thread
    //   rows arow and arow+64; k-range ak..ak+7
    int arow = tid >> 1;            // 0..63
    int ak   = (tid & 1) * 8;       // 0 or 8
    // B loads: 16 rows x 128 cols = 2048 floats; 16 per thread
    //   rows brow, brow+4, brow+8, brow+12
    int brow = tid >> 5;            // 0..3
    int bcol = (tid & 31) * 4;      // 0..124

    int tx = tid & 15;              // n-group: cols n0 + tx*8 .. +7
    int ty = tid >> 4;              // m-group: rows ty*8..+7 and 64+ty*8..+7

    const float* Aptr0 = A + (m0 + arow) * K + ak;
    const float* Aptr1 = A + (m0 + 64 + arow) * K + ak;
    const float* Bptr0 = B + brow * N + n0 + bcol;
    const float* Bptr1 = B + (brow + 4) * N + n0 + bcol;
    const float* Bptr2 = B + (brow + 8) * N + n0 + bcol;
    const float* Bptr3 = B + (brow + 12) * N + n0 + bcol;

    u64 acc[16][4];
    #pragma unroll
    for (int r = 0; r < 16; r++)
        #pragma unroll
        for (int c = 0; c < 4; c++) acc[r][c] = 0ull;

    float4 a00 = *(const float4*)Aptr0;
    float4 a01 = *(const float4*)(Aptr0 + 4);
    float4 a10 = *(const float4*)Aptr1;
    float4 a11 = *(const float4*)(Aptr1 + 4);
    float4 bv0 = *(const float4*)Bptr0;
    float4 bv1 = *(const float4*)Bptr1;
    float4 bv2 = *(const float4*)Bptr2;
    float4 bv3 = *(const float4*)Bptr3;

    // store tile 0 (A transposed scalar)
    As[0][ak + 0][arow] = a00.x;  As[0][ak + 1][arow] = a00.y;
    As[0][ak + 2][arow] = a00.z;  As[0][ak + 3][arow] = a00.w;
    As[0][ak + 4][arow] = a01.x;  As[0][ak + 5][arow] = a01.y;
    As[0][ak + 6][arow] = a01.z;  As[0][ak + 7][arow] = a01.w;
    As[0][ak + 0][arow + 64] = a10.x;  As[0][ak + 1][arow + 64] = a10.y;
    As[0][ak + 2][arow + 64] = a10.z;  As[0][ak + 3][arow + 64] = a10.w;
    As[0][ak + 4][arow + 64] = a11.x;  As[0][ak + 5][arow + 64] = a11.y;
    As[0][ak + 6][arow + 64] = a11.z;  As[0][ak + 7][arow + 64] = a11.w;
    *(float4*)&Bs[0][brow][bcol]      = bv0;
    *(float4*)&Bs[0][brow + 4][bcol]  = bv1;
    *(float4*)&Bs[0][brow + 8][bcol]  = bv2;
    *(float4*)&Bs[0][brow + 12][bcol] = bv3;
    __syncthreads();

    for (int t = 0; t < GNK; t++) {
        int buf = t & 1;
        if (t + 1 < GNK) {
            a00 = *(const float4*)(Aptr0 + (t + 1) * GBK);
            a01 = *(const float4*)(Aptr0 + (t + 1) * GBK + 4);
            a10 = *(const float4*)(Aptr1 + (t + 1) * GBK);
            a11 = *(const float4*)(Aptr1 + (t + 1) * GBK + 4);
            bv0 = *(const float4*)(Bptr0 + (size_t)(t + 1) * GBK * N);
            bv1 = *(const float4*)(Bptr1 + (size_t)(t + 1) * GBK * N);
            bv2 = *(const float4*)(Bptr2 + (size_t)(t + 1) * GBK * N);
            bv3 = *(const float4*)(Bptr3 + (size_t)(t + 1) * GBK * N);
        }

        #pragma unroll
        for (int kk = 0; kk < GBK; kk++) {
            float4 af0 = *(const float4*)&As[buf][kk][ty * 8];
            float4 af1 = *(const float4*)&As[buf][kk][ty * 8 + 4];
            float4 af2 = *(const float4*)&As[buf][kk][64 + ty * 8];
            float4 af3 = *(const float4*)&As[buf][kk][64 + ty * 8 + 4];
            ulonglong2 b01 = *(const ulonglong2*)&Bs[buf][kk][tx * 8];
            ulonglong2 b23 = *(const ulonglong2*)&Bs[buf][kk][tx * 8 + 4];

            float am[16] = { af0.x, af0.y, af0.z, af0.w, af1.x, af1.y, af1.z, af1.w,
                             af2.x, af2.y, af2.z, af2.w, af3.x, af3.y, af3.z, af3.w };
            #pragma unroll
            for (int r = 0; r < 16; r++) {
                u64 ad = fdup(am[r]);
                acc[r][0] = ffma2(ad, b01.x, acc[r][0]);
                acc[r][1] = ffma2(ad, b01.y, acc[r][1]);
                acc[r][2] = ffma2(ad, b23.x, acc[r][2]);
                acc[r][3] = ffma2(ad, b23.y, acc[r][3]);
            }
        }

        if (t + 1 < GNK) {
            int nb = buf ^ 1;
            As[nb][ak + 0][arow] = a00.x;  As[nb][ak + 1][arow] = a00.y;
            As[nb][ak + 2][arow] = a00.z;  As[nb][ak + 3][arow] = a00.w;
            As[nb][ak + 4][arow] = a01.x;  As[nb][ak + 5][arow] = a01.y;
            As[nb][ak + 6][arow] = a01.z;  As[nb][ak + 7][arow] = a01.w;
            As[nb][ak + 0][arow + 64] = a10.x;  As[nb][ak + 1][arow + 64] = a10.y;
            As[nb][ak + 2][arow + 64] = a10.z;  As[nb][ak + 3][arow + 64] = a10.w;
            As[nb][ak + 4][arow + 64] = a11.x;  As[nb][ak + 5][arow + 64] = a11.y;
            As[nb][ak + 6][arow + 64] = a11.z;  As[nb][ak + 7][arow + 64] = a11.w;
            *(float4*)&Bs[nb][brow][bcol]      = bv0;
            *(float4*)&Bs[nb][brow + 4][bcol]  = bv1;
            *(float4*)&Bs[nb][brow + 8][bcol]  = bv2;
            *(float4*)&Bs[nb][brow + 12][bcol] = bv3;
        }
        __syncthreads();
    }

    #pragma unroll
    for (int r = 0; r < 16; r++) {
        int row = (r < 8) ? (m0 + ty * 8 + r) : (m0 + 64 + ty * 8 + (r - 8));
        float2 c0 = funpack(acc[r][0]);
        float2 c1 = funpack(acc[r][1]);
        float2 c2 = funpack(acc[r][2]);
        float2 c3 = funpack(acc[r][3]);
        *(float4*)&C[row * N + n0 + tx * 8]     = make_float4(c0.x, c0.y, c1.x, c1.y);
        *(float4*)&C[row * N + n0 + tx * 8 + 4] = make_float4(c2.x, c2.y, c3.x, c3.y);
    }
}

__global__ __launch_bounds__(128) void gemm3_kernel(const float* __restrict__ q,
                                                    const float* __restrict__ qw,
                                                    const float* __restrict__ k,
                                                    const float* __restrict__ kw,
                                                    const float* __restrict__ v,
                                                    const float* __restrict__ vw) {
    const float* A;
    const float* B;
    float* C;
    if (blockIdx.z == 0)      { A = q; B = qw; C = g_wq; }
    else if (blockIdx.z == 1) { A = k; B = kw; C = g_wk; }
    else                      { A = v; B = vw; C = g_wv; }
    sgemm_tile(A, B, C, MDIM, MDIM);
}

__global__ __launch_bounds__(128) void gemm_out_kernel(const float* __restrict__ ow,
                                                       float* __restrict__ out) {
    sgemm_tile(g_heads, ow, out, MDIM, MDIM);
}

// ---------------- pass A: per-(h,j) column stats over i, fused vt = wv/D ----------------
// grid: (J/128, NHEAD), block 128. Thread owns one column j of head h.
__global__ __launch_bounds__(128) void stats_kernel() {
    int h = blockIdx.y;
    int j = blockIdx.x * 128 + threadIdx.x;
    int c0 = h * HD;

    u64 kp[8];     // 16 k-values as 8 pairs
    {
        const ulonglong2* krow = (const ulonglong2*)&g_wk[j * MDIM + c0];
        #pragma unroll
        for (int k = 0; k < 4; k++) {
            ulonglong2 t = krow[k];
            kp[2 * k] = t.x; kp[2 * k + 1] = t.y;
        }
    }

    __shared__ float sq[128][20];   // 80B row stride (16B aligned)

    float m = -1e30f;
    float D = 0.0f;

    for (int i0 = 0; i0 < I_LEN; i0 += 128) {
        __syncthreads();
        {
            int t = threadIdx.x;
            const float* qrow = &g_wq[(i0 + t) * MDIM + c0];
            #pragma unroll
            for (int k = 0; k < 16; k += 4)
                *(float4*)&sq[t][k] = *(const float4*)&qrow[k];
        }
        __syncthreads();

        #pragma unroll 4
        for (int ii = 0; ii < 128; ii++) {
            ulonglong2 q01 = *(const ulonglong2*)&sq[ii][0];
            ulonglong2 q23 = *(const ulonglong2*)&sq[ii][4];
            ulonglong2 q45 = *(const ulonglong2*)&sq[ii][8];
            ulonglong2 q67 = *(const ulonglong2*)&sq[ii][12];
            u64 pA = 0ull, pB = 0ull;        // pA lanes: s0,s1 ; pB lanes: s2,s3
            pA = ffma2(kp[0], q01.x, pA);  pB = ffma2(kp[1], q01.y, pB);
            pA = ffma2(kp[2], q23.x, pA);  pB = ffma2(kp[3], q23.y, pB);
            pA = ffma2(kp[4], q45.x, pA);  pB = ffma2(kp[5], q45.y, pB);
            pA = ffma2(kp[6], q67.x, pA);  pB = ffma2(kp[7], q67.y, pB);
            float2 fa = funpack(pA);
            float2 fb = funpack(pB);
            float s = ((fa.x + fa.y) + (fb.x + fb.y)) * CSCALE;   // log2-domain logit
            // branch-free online update; ex2(0)==1.0 exactly on the common path
            float mn = fmaxf(m, s);
            float e_old = fexp2(m - mn);
            float e_new = fexp2(s - mn);
            D = __fmaf_rn(D, e_old, e_new);
            m = mn;
        }
    }

    float invd = 1.0f / D;
    g_m[h * J_LEN + j] = m;

    // fused vtilde: vt[j,h,:] = wv[j,h,:] * invd
    {
        const float* vr  = &g_wv[j * MDIM + c0];
        float*       vtr = &g_vt[j * MDIM + c0];
        #pragma unroll
        for (int k = 0; k < 16; k += 4) {
            float4 t = *(const float4*)&vr[k];
            t.x *= invd; t.y *= invd; t.z *= invd; t.w *= invd;
            *(float4*)&vtr[k] = t;
        }
    }
}

// ---------------- pass B: heads[i,h,:] = sum_j 2^(s-m) * vt[j,h,:] ----------------
// grid: (I/256, NHEAD), block 128; each thread owns 2 i-rows. FFMA2 everywhere.
__global__ __launch_bounds__(128) void attn_kernel() {
    int h = blockIdx.y;
    int c0 = h * HD;
    int ia = blockIdx.x * 256 + threadIdx.x;
    int ib = ia + 128;

    u64 qa[8], qb[8], aa[8], ab[8];
    {
        const ulonglong2* ra = (const ulonglong2*)&g_wq[ia * MDIM + c0];
        const ulonglong2* rb = (const ulonglong2*)&g_wq[ib * MDIM + c0];
        #pragma unroll
        for (int k = 0; k < 4; k++) {
            ulonglong2 t = ra[k];
            qa[2 * k] = t.x; qa[2 * k + 1] = t.y;
            ulonglong2 u = rb[k];
            qb[2 * k] = u.x; qb[2 * k + 1] = u.y;
        }
    }
    #pragma unroll
    for (int v = 0; v < 8; v++) { aa[v] = 0ull; ab[v] = 0ull; }

    __shared__ float sk[128][20];
    __shared__ float sv[128][20];
    __shared__ float sm[128];

    for (int j0 = 0; j0 < J_LEN; j0 += 128) {
        __syncthreads();
        {
            int t = threadIdx.x;
            const float* krow = &g_wk[(j0 + t) * MDIM + c0];
            const float* vrow = &g_vt[(j0 + t) * MDIM + c0];
            #pragma unroll
            for (int k = 0; k < 16; k += 4) {
                *(float4*)&sk[t][k] = *(const float4*)&krow[k];
                *(float4*)&sv[t][k] = *(const float4*)&vrow[k];
            }
            sm[t] = g_m[h * J_LEN + j0 + t];
        }
        __syncthreads();

        #pragma unroll 2
        for (int jj = 0; jj < 128; jj++) {
            ulonglong2 k01 = *(const ulonglong2*)&sk[jj][0];
            ulonglong2 k23 = *(const ulonglong2*)&sk[jj][4];
            ulonglong2 k45 = *(const ulonglong2*)&sk[jj][8];
            ulonglong2 k67 = *(const ulonglong2*)&sk[jj][12];

            u64 pAa = 0ull, pBa = 0ull, pAb = 0ull, pBb = 0ull;
            pAa = ffma2(k01.x, qa[0], pAa);  pBa = ffma2(k01.y, qa[1], pBa);
            pAb = ffma2(k01.x, qb[0], pAb);  pBb = ffma2(k01.y, qb[1], pBb);
            pAa = ffma2(k23.x, qa[2], pAa);  pBa = ffma2(k23.y, qa[3], pBa);
            pAb = ffma2(k23.x, qb[2], pAb);  pBb = ffma2(k23.y, qb[3], pBb);
            pAa = ffma2(k45.x, qa[4], pAa);  pBa = ffma2(k45.y, qa[5], pBa);
            pAb = ffma2(k45.x, qb[4], pAb);  pBb = ffma2(k45.y, qb[5], pBb);
            pAa = ffma2(k67.x, qa[6], pAa);  pBa = ffma2(k67.y, qa[7], pBa);
            pAb = ffma2(k67.x, qb[6], pAb);  pBb = ffma2(k67.y, qb[7], pBb);

            float2 a1 = funpack(pAa), a2 = funpack(pBa);
            float2 b1 = funpack(pAb), b2 = funpack(pBb);
            float sa = (a1.x + a1.y) + (a2.x + a2.y);   // same tree as stats
            float sb = (b1.x + b1.y) + (b2.x + b2.y);
            float mj = sm[jj];
            float ea = fexp2(__fmaf_rn(sa, CSCALE, -mj));
            float eb = fexp2(__fmaf_rn(sb, CSCALE, -mj));
            u64 ed = fdup(ea);
            u64 fd = fdup(eb);

            ulonglong2 v01 = *(const ulonglong2*)&sv[jj][0];
            ulonglong2 v23 = *(const ulonglong2*)&sv[jj][4];
            ulonglong2 v45 = *(const ulonglong2*)&sv[jj][8];
            ulonglong2 v67 = *(const ulonglong2*)&sv[jj][12];
            u64 vr[8] = { v01.x, v01.y, v23.x, v23.y, v45.x, v45.y, v67.x, v67.y };
            #pragma unroll
            for (int v = 0; v < 8; v++) {
                aa[v] = ffma2(ed, vr[v], aa[v]);
                ab[v] = ffma2(fd, vr[v], ab[v]);
            }
        }
    }

    {
        float* oa = &g_heads[ia * MDIM + c0];
        float* ob = &g_heads[ib * MDIM + c0];
        #pragma unroll
        for (int k = 0; k < 4; k++) {
            float2 p0 = funpack(aa[2 * k]);
            float2 p1 = funpack(aa[2 * k + 1]);
            *(float4*)&oa[4 * k] = make_float4(p0.x, p0.y, p1.x, p1.y);
            float2 r0 = funpack(ab[2 * k]);
            float2 r1 = funpack(ab[2 * k + 1]);
            *(float4*)&ob[4 * k] = make_float4(r0.x, r0.y, r1.x, r1.y);
        }
    }
}

// ---------------- launch ----------------
extern "C" void kernel_launch(void* const* d_in, const int* in_sizes, int n_in,
                              void* d_out, int out_size) {
    (void)in_sizes; (void)n_in; (void)out_size;
    const float* q  = (const float*)d_in[0];
    const float* k  = (const float*)d_in[1];
    const float* v  = (const float*)d_in[2];
    const float* qw = (const float*)d_in[3];
    const float* kw = (const float*)d_in[4];
    const float* vw = (const float*)d_in[5];
    const float* ow = (const float*)d_in[6];
    float* out = (float*)d_out;

    dim3 ggrid3(MDIM / GBN, I_LEN / GBM, 3);
    gemm3_kernel<<<ggrid3, 128>>>(q, qw, k, kw, v, vw);

    stats_kernel<<<dim3(J_LEN / 128, NHEAD), 128>>>();

    attn_kernel<<<dim3(I_LEN / 256, NHEAD), 128>>>();

    gemm_out_kernel<<<dim3(MDIM / GBN, I_LEN / GBM), 128>>>(ow, out);
}

// round 11
// speedup vs baseline: 1.1274x; 1.0081x over previous
#include <cuda_runtime.h>

// Problem constants
#define I_LEN 2048
#define J_LEN 2048
#define MDIM  1024
#define NHEAD 64     // "head" axis (weights dim1)
#define HD    16     // per-head contracted feature dim (weights dim2)

// combined scale: (1/sqrt(64)) * log2(e)  -- logits kept in log2 domain
#define CSCALE 0.18033688011112042f

typedef unsigned long long u64;

// ---------------- scratch (static device globals; no allocation) ----------------
__device__ float g_wq[I_LEN * MDIM];
__device__ float g_wk[J_LEN * MDIM];
__device__ float g_wv[J_LEN * MDIM];
__device__ float g_vt[J_LEN * MDIM];      // wv * invD (written by stats; idempotent)
__device__ float g_heads[I_LEN * MDIM];
__device__ float g_m[NHEAD * J_LEN];      // column max of log2-scaled logits

// ---------------- packed fp32x2 FMA (Blackwell sm_100+) ----------------
__device__ __forceinline__ u64 ffma2(u64 a, u64 b, u64 c) {
    u64 d;
    asm("fma.rn.f32x2 %0, %1, %2, %3;" : "=l"(d) : "l"(a), "l"(b), "l"(c));
    return d;
}
__device__ __forceinline__ u64 fdup(float x) {
    u64 d;
    asm("mov.b64 %0, {%1, %1};" : "=l"(d) : "f"(x));
    return d;
}
__device__ __forceinline__ float2 funpack(u64 p) {
    float2 r;
    asm("mov.b64 {%0, %1}, %2;" : "=f"(r.x), "=f"(r.y) : "l"(p));
    return r;
}

// ---------------- exp2 on the MUFU pipe ----------------
__device__ __forceinline__ float fexp2(float x) {
    float y;
    asm("ex2.approx.ftz.f32 %0, %1;" : "=f"(y) : "f"(x));
    return y;
}

// ---------------- SGEMM: C[2048x1024] = A[2048xK] @ B[Kx1024], K=1024 ----------------
// 128x64 tile (M x N), BK=16, 128 threads, 16m x 4n microtile per thread.
// Crossbar:FMA per kk = 5 LDS.128 (20 cyc) : 32 FFMA2 (64 cyc) = 0.31 -> FMA-bound.
// grid per GEMM = 16x16 = 256 blocks; 2 blocks/SM (8 warps, 2/SMSP).
// A in smem transposed scalar (As[k][m]); fdup'd in-register (MOVs fit issue gaps).
#define GBM 128
#define GBN 64
#define GBK 16
#define GNK (MDIM / GBK)

__device__ __forceinline__ void sgemm_tile(const float* __restrict__ A,
                                           const float* __restrict__ B,
                                           float* __restrict__ C,
                                           int N, int K) {
    __shared__ float As[2][GBK][GBM];   // transposed: As[k][m], 8KB per buffer
    __shared__ float Bs[2][GBK][GBN];   // 4KB per buffer

    int tid = threadIdx.x;   // 0..127
    int m0 = blockIdx.y * GBM;
    int n0 = blockIdx.x * GBN;

    // A loads: 128 rows x 16 k = 2048 floats; 16 per thread
    //   rows arow and arow+64; k-range ak..ak+7
    int arow = tid >> 1;            // 0..63
    int ak   = (tid & 1) * 8;       // 0 or 8
    // B loads: 16 rows x 64 cols = 1024 floats; 8 per thread (rows brow, brow+8)
    int brow = tid >> 4;            // 0..7
    int bcol = (tid & 15) * 4;      // 0..60

    int tx = tid & 15;              // n-group: cols n0 + tx*4 .. +3
    int ty = tid >> 4;              // m-group (0..7): rows ty*8..+7 and 64+ty*8..+7

    const float* Aptr0 = A + (m0 + arow) * K + ak;
    const float* Aptr1 = A + (m0 + 64 + arow) * K + ak;
    const float* Bptr0 = B + brow * N + n0 + bcol;
    const float* Bptr1 = B + (brow + 8) * N + n0 + bcol;

    u64 acc[16][2];
    #pragma unroll
    for (int r = 0; r < 16; r++) { acc[r][0] = 0ull; acc[r][1] = 0ull; }

    float4 a00 = *(const float4*)Aptr0;
    float4 a01 = *(const float4*)(Aptr0 + 4);
    float4 a10 = *(const float4*)Aptr1;
    float4 a11 = *(const float4*)(Aptr1 + 4);
    float4 bv0 = *(const float4*)Bptr0;
    float4 bv1 = *(const float4*)Bptr1;

    // store tile 0 (A transposed scalar)
    As[0][ak + 0][arow] = a00.x;  As[0][ak + 1][arow] = a00.y;
    As[0][ak + 2][arow] = a00.z;  As[0][ak + 3][arow] = a00.w;
    As[0][ak + 4][arow] = a01.x;  As[0][ak + 5][arow] = a01.y;
    As[0][ak + 6][arow] = a01.z;  As[0][ak + 7][arow] = a01.w;
    As[0][ak + 0][arow + 64] = a10.x;  As[0][ak + 1][arow + 64] = a10.y;
    As[0][ak + 2][arow + 64] = a10.z;  As[0][ak + 3][arow + 64] = a10.w;
    As[0][ak + 4][arow + 64] = a11.x;  As[0][ak + 5][arow + 64] = a11.y;
    As[0][ak + 6][arow + 64] = a11.z;  As[0][ak + 7][arow + 64] = a11.w;
    *(float4*)&Bs[0][brow][bcol]     = bv0;
    *(float4*)&Bs[0][brow + 8][bcol] = bv1;
    __syncthreads();

    for (int t = 0; t < GNK; t++) {
        int buf = t & 1;
        if (t + 1 < GNK) {
            a00 = *(const float4*)(Aptr0 + (t + 1) * GBK);
            a01 = *(const float4*)(Aptr0 + (t + 1) * GBK + 4);
            a10 = *(const float4*)(Aptr1 + (t + 1) * GBK);
            a11 = *(const float4*)(Aptr1 + (t + 1) * GBK + 4);
            bv0 = *(const float4*)(Bptr0 + (size_t)(t + 1) * GBK * N);
            bv1 = *(const float4*)(Bptr1 + (size_t)(t + 1) * GBK * N);
        }

        #pragma unroll
        for (int kk = 0; kk < GBK; kk++) {
            float4 af0 = *(const float4*)&As[buf][kk][ty * 8];
            float4 af1 = *(const float4*)&As[buf][kk][ty * 8 + 4];
            float4 af2 = *(const float4*)&As[buf][kk][64 + ty * 8];
            float4 af3 = *(const float4*)&As[buf][kk][64 + ty * 8 + 4];
            ulonglong2 b01 = *(const ulonglong2*)&Bs[buf][kk][tx * 4];

            float am[16] = { af0.x, af0.y, af0.z, af0.w, af1.x, af1.y, af1.z, af1.w,
                             af2.x, af2.y, af2.z, af2.w, af3.x, af3.y, af3.z, af3.w };
            #pragma unroll
            for (int r = 0; r < 16; r++) {
                u64 ad = fdup(am[r]);
                acc[r][0] = ffma2(ad, b01.x, acc[r][0]);
                acc[r][1] = ffma2(ad, b01.y, acc[r][1]);
            }
        }

        if (t + 1 < GNK) {
            int nb = buf ^ 1;
            As[nb][ak + 0][arow] = a00.x;  As[nb][ak + 1][arow] = a00.y;
            As[nb][ak + 2][arow] = a00.z;  As[nb][ak + 3][arow] = a00.w;
            As[nb][ak + 4][arow] = a01.x;  As[nb][ak + 5][arow] = a01.y;
            As[nb][ak + 6][arow] = a01.z;  As[nb][ak + 7][arow] = a01.w;
            As[nb][ak + 0][arow + 64] = a10.x;  As[nb][ak + 1][arow + 64] = a10.y;
            As[nb][ak + 2][arow + 64] = a10.z;  As[nb][ak + 3][arow + 64] = a10.w;
            As[nb][ak + 4][arow + 64] = a11.x;  As[nb][ak + 5][arow + 64] = a11.y;
            As[nb][ak + 6][arow + 64] = a11.z;  As[nb][ak + 7][arow + 64] = a11.w;
            *(float4*)&Bs[nb][brow][bcol]     = bv0;
            *(float4*)&Bs[nb][brow + 8][bcol] = bv1;
        }
        __syncthreads();
    }

    #pragma unroll
    for (int r = 0; r < 16; r++) {
        int row = (r < 8) ? (m0 + ty * 8 + r) : (m0 + 64 + ty * 8 + (r - 8));
        float2 c0 = funpack(acc[r][0]);
        float2 c1 = funpack(acc[r][1]);
        *(float4*)&C[row * N + n0 + tx * 4] = make_float4(c0.x, c0.y, c1.x, c1.y);
    }
}

__global__ __launch_bounds__(128, 2) void gemm3_kernel(const float* __restrict__ q,
                                                       const float* __restrict__ qw,
                                                       const float* __restrict__ k,
                                                       const float* __restrict__ kw,
                                                       const float* __restrict__ v,
                                                       const float* __restrict__ vw) {
    const float* A;
    const float* B;
    float* C;
    if (blockIdx.z == 0)      { A = q; B = qw; C = g_wq; }
    else if (blockIdx.z == 1) { A = k; B = kw; C = g_wk; }
    else                      { A = v; B = vw; C = g_wv; }
    sgemm_tile(A, B, C, MDIM, MDIM);
}

__global__ __launch_bounds__(128, 2) void gemm_out_kernel(const float* __restrict__ ow,
                                                          float* __restrict__ out) {
    sgemm_tile(g_heads, ow, out, MDIM, MDIM);
}

// ---------------- pass A: per-(h,j) column stats over i, fused vt = wv/D ----------------
// grid: (J/128, NHEAD), block 128. Thread owns one column j of head h.
__global__ __launch_bounds__(128) void stats_kernel() {
    int h = blockIdx.y;
    int j = blockIdx.x * 128 + threadIdx.x;
    int c0 = h * HD;

    u64 kp[8];     // 16 k-values as 8 pairs
    {
        const ulonglong2* krow = (const ulonglong2*)&g_wk[j * MDIM + c0];
        #pragma unroll
        for (int k = 0; k < 4; k++) {
            ulonglong2 t = krow[k];
            kp[2 * k] = t.x; kp[2 * k + 1] = t.y;
        }
    }

    __shared__ float sq[128][20];   // 80B row stride (16B aligned)

    float m = -1e30f;
    float D = 0.0f;

    for (int i0 = 0; i0 < I_LEN; i0 += 128) {
        __syncthreads();
        {
            int t = threadIdx.x;
            const float* qrow = &g_wq[(i0 + t) * MDIM + c0];
            #pragma unroll
            for (int k = 0; k < 16; k += 4)
                *(float4*)&sq[t][k] = *(const float4*)&qrow[k];
        }
        __syncthreads();

        #pragma unroll 4
        for (int ii = 0; ii < 128; ii++) {
            ulonglong2 q01 = *(const ulonglong2*)&sq[ii][0];
            ulonglong2 q23 = *(const ulonglong2*)&sq[ii][4];
            ulonglong2 q45 = *(const ulonglong2*)&sq[ii][8];
            ulonglong2 q67 = *(const ulonglong2*)&sq[ii][12];
            u64 pA = 0ull, pB = 0ull;        // pA lanes: s0,s1 ; pB lanes: s2,s3
            pA = ffma2(kp[0], q01.x, pA);  pB = ffma2(kp[1], q01.y, pB);
            pA = ffma2(kp[2], q23.x, pA);  pB = ffma2(kp[3], q23.y, pB);
            pA = ffma2(kp[4], q45.x, pA);  pB = ffma2(kp[5], q45.y, pB);
            pA = ffma2(kp[6], q67.x, pA);  pB = ffma2(kp[7], q67.y, pB);
            float2 fa = funpack(pA);
            float2 fb = funpack(pB);
            float s = ((fa.x + fa.y) + (fb.x + fb.y)) * CSCALE;   // log2-domain logit
            // branch-free online update; ex2(0)==1.0 exactly on the common path
            float mn = fmaxf(m, s);
            float e_old = fexp2(m - mn);
            float e_new = fexp2(s - mn);
            D = __fmaf_rn(D, e_old, e_new);
            m = mn;
        }
    }

    float invd = 1.0f / D;
    g_m[h * J_LEN + j] = m;

    // fused vtilde: vt[j,h,:] = wv[j,h,:] * invd
    {
        const float* vr  = &g_wv[j * MDIM + c0];
        float*       vtr = &g_vt[j * MDIM + c0];
        #pragma unroll
        for (int k = 0; k < 16; k += 4) {
            float4 t = *(const float4*)&vr[k];
            t.x *= invd; t.y *= invd; t.z *= invd; t.w *= invd;
            *(float4*)&vtr[k] = t;
        }
    }
}

// ---------------- pass B: heads[i,h,:] = sum_j 2^(s-m) * vt[j,h,:] ----------------
// grid: (I/256, NHEAD), block 128; each thread owns 2 i-rows. FFMA2 everywhere.
__global__ __launch_bounds__(128) void attn_kernel() {
    int h = blockIdx.y;
    int c0 = h * HD;
    int ia = blockIdx.x * 256 + threadIdx.x;
    int ib = ia + 128;

    u64 qa[8], qb[8], aa[8], ab[8];
    {
        const ulonglong2* ra = (const ulonglong2*)&g_wq[ia * MDIM + c0];
        const ulonglong2* rb = (const ulonglong2*)&g_wq[ib * MDIM + c0];
        #pragma unroll
        for (int k = 0; k < 4; k++) {
            ulonglong2 t = ra[k];
            qa[2 * k] = t.x; qa[2 * k + 1] = t.y;
            ulonglong2 u = rb[k];
            qb[2 * k] = u.x; qb[2 * k + 1] = u.y;
        }
    }
    #pragma unroll
    for (int v = 0; v < 8; v++) { aa[v] = 0ull; ab[v] = 0ull; }

    __shared__ float sk[128][20];
    __shared__ float sv[128][20];
    __shared__ float sm[128];

    for (int j0 = 0; j0 < J_LEN; j0 += 128) {
        __syncthreads();
        {
            int t = threadIdx.x;
            const float* krow = &g_wk[(j0 + t) * MDIM + c0];
            const float* vrow = &g_vt[(j0 + t) * MDIM + c0];
            #pragma unroll
            for (int k = 0; k < 16; k += 4) {
                *(float4*)&sk[t][k] = *(const float4*)&krow[k];
                *(float4*)&sv[t][k] = *(const float4*)&vrow[k];
            }
            sm[t] = g_m[h * J_LEN + j0 + t];
        }
        __syncthreads();

        #pragma unroll 2
        for (int jj = 0; jj < 128; jj++) {
            ulonglong2 k01 = *(const ulonglong2*)&sk[jj][0];
            ulonglong2 k23 = *(const ulonglong2*)&sk[jj][4];
            ulonglong2 k45 = *(const ulonglong2*)&sk[jj][8];
            ulonglong2 k67 = *(const ulonglong2*)&sk[jj][12];

            u64 pAa = 0ull, pBa = 0ull, pAb = 0ull, pBb = 0ull;
            pAa = ffma2(k01.x, qa[0], pAa);  pBa = ffma2(k01.y, qa[1], pBa);
            pAb = ffma2(k01.x, qb[0], pAb);  pBb = ffma2(k01.y, qb[1], pBb);
            pAa = ffma2(k23.x, qa[2], pAa);  pBa = ffma2(k23.y, qa[3], pBa);
            pAb = ffma2(k23.x, qb[2], pAb);  pBb = ffma2(k23.y, qb[3], pBb);
            pAa = ffma2(k45.x, qa[4], pAa);  pBa = ffma2(k45.y, qa[5], pBa);
            pAb = ffma2(k45.x, qb[4], pAb);  pBb = ffma2(k45.y, qb[5], pBb);
            pAa = ffma2(k67.x, qa[6], pAa);  pBa = ffma2(k67.y, qa[7], pBa);
            pAb = ffma2(k67.x, qb[6], pAb);  pBb = ffma2(k67.y, qb[7], pBb);

            float2 a1 = funpack(pAa), a2 = funpack(pBa);
            float2 b1 = funpack(pAb), b2 = funpack(pBb);
            float sa = (a1.x + a1.y) + (a2.x + a2.y);   // same tree as stats
            float sb = (b1.x + b1.y) + (b2.x + b2.y);
            float mj = sm[jj];
            float ea = fexp2(__fmaf_rn(sa, CSCALE, -mj));
            float eb = fexp2(__fmaf_rn(sb, CSCALE, -mj));
            u64 ed = fdup(ea);
            u64 fd = fdup(eb);

            ulonglong2 v01 = *(const ulonglong2*)&sv[jj][0];
            ulonglong2 v23 = *(const ulonglong2*)&sv[jj][4];
            ulonglong2 v45 = *(const ulonglong2*)&sv[jj][8];
            ulonglong2 v67 = *(const ulonglong2*)&sv[jj][12];
            u64 vr[8] = { v01.x, v01.y, v23.x, v23.y, v45.x, v45.y, v67.x, v67.y };
            #pragma unroll
            for (int v = 0; v < 8; v++) {
                aa[v] = ffma2(ed, vr[v], aa[v]);
                ab[v] = ffma2(fd, vr[v], ab[v]);
            }
        }
    }

    {
        float* oa = &g_heads[ia * MDIM + c0];
        float* ob = &g_heads[ib * MDIM + c0];
        #pragma unroll
        for (int k = 0; k < 4; k++) {
            float2 p0 = funpack(aa[2 * k]);
            float2 p1 = funpack(aa[2 * k + 1]);
            *(float4*)&oa[4 * k] = make_float4(p0.x, p0.y, p1.x, p1.y);
            float2 r0 = funpack(ab[2 * k]);
            float2 r1 = funpack(ab[2 * k + 1]);
            *(float4*)&ob[4 * k] = make_float4(r0.x, r0.y, r1.x, r1.y);
        }
    }
}

// ---------------- launch ----------------
extern "C" void kernel_launch(void* const* d_in, const int* in_sizes, int n_in,
                              void* d_out, int out_size) {
    (void)in_sizes; (void)n_in; (void)out_size;
    const float* q  = (const float*)d_in[0];
    const float* k  = (const float*)d_in[1];
    const float* v  = (const float*)d_in[2];
    const float* qw = (const float*)d_in[3];
    const float* kw = (const float*)d_in[4];
    const float* vw = (const float*)d_in[5];
    const float* ow = (const float*)d_in[6];
    float* out = (float*)d_out;

    dim3 ggrid3(MDIM / GBN, I_LEN / GBM, 3);
    gemm3_kernel<<<ggrid3, 128>>>(q, qw, k, kw, v, vw);

    stats_kernel<<<dim3(J_LEN / 128, NHEAD), 128>>>();

    attn_kernel<<<dim3(I_LEN / 256, NHEAD), 128>>>();

    gemm_out_kernel<<<dim3(MDIM / GBN, I_LEN / GBM), 128>>>(ow, out);
}

// round 12
// speedup vs baseline: 1.1530x; 1.0227x over previous
#include <cuda_runtime.h>

// Problem constants
#define I_LEN 2048
#define J_LEN 2048
#define MDIM  1024
#define NHEAD 64     // "head" axis (weights dim1)
#define HD    16     // per-head contracted feature dim (weights dim2)

// combined scale: (1/sqrt(64)) * log2(e)  -- logits kept in log2 domain
#define CSCALE 0.18033688011112042f

typedef unsigned long long u64;

// ---------------- scratch (static device globals; no allocation) ----------------
__device__ float g_wq[I_LEN * MDIM];
__device__ float g_wk[J_LEN * MDIM];
__device__ float g_wv[J_LEN * MDIM];
__device__ float g_vt[J_LEN * MDIM];      // wv * invD (written by stats; idempotent)
__device__ float g_heads[I_LEN * MDIM];
__device__ float g_m[NHEAD * J_LEN];      // column max of log2-scaled logits
__device__ float g_s[(size_t)NHEAD * I_LEN * J_LEN];  // raw dot sdot[h][i][j] (1 GiB)

// ---------------- packed fp32x2 FMA (Blackwell sm_100+) ----------------
__device__ __forceinline__ u64 ffma2(u64 a, u64 b, u64 c) {
    u64 d;
    asm("fma.rn.f32x2 %0, %1, %2, %3;" : "=l"(d) : "l"(a), "l"(b), "l"(c));
    return d;
}
__device__ __forceinline__ u64 fdup(float x) {
    u64 d;
    asm("mov.b64 %0, {%1, %1};" : "=l"(d) : "f"(x));
    return d;
}
__device__ __forceinline__ float2 funpack(u64 p) {
    float2 r;
    asm("mov.b64 {%0, %1}, %2;" : "=f"(r.x), "=f"(r.y) : "l"(p));
    return r;
}

// ---------------- exp2 on the MUFU pipe ----------------
__device__ __forceinline__ float fexp2(float x) {
    float y;
    asm("ex2.approx.ftz.f32 %0, %1;" : "=f"(y) : "f"(x));
    return y;
}

// ---------------- SGEMM: C[2048x1024] = A[2048xK] @ B[Kx1024], K=1024 ----------------
// 128x64 tile (M x N), BK=16, 128 threads, 16m x 4n microtile per thread. (unchanged)
#define GBM 128
#define GBN 64
#define GBK 16
#define GNK (MDIM / GBK)

__device__ __forceinline__ void sgemm_tile(const float* __restrict__ A,
                                           const float* __restrict__ B,
                                           float* __restrict__ C,
                                           int N, int K) {
    __shared__ float As[2][GBK][GBM];   // transposed: As[k][m], 8KB per buffer
    __shared__ float Bs[2][GBK][GBN];   // 4KB per buffer

    int tid = threadIdx.x;   // 0..127
    int m0 = blockIdx.y * GBM;
    int n0 = blockIdx.x * GBN;

    int arow = tid >> 1;            // 0..63
    int ak   = (tid & 1) * 8;       // 0 or 8
    int brow = tid >> 4;            // 0..7
    int bcol = (tid & 15) * 4;      // 0..60

    int tx = tid & 15;              // n-group: cols n0 + tx*4 .. +3
    int ty = tid >> 4;              // m-group (0..7)

    const float* Aptr0 = A + (m0 + arow) * K + ak;
    const float* Aptr1 = A + (m0 + 64 + arow) * K + ak;
    const float* Bptr0 = B + brow * N + n0 + bcol;
    const float* Bptr1 = B + (brow + 8) * N + n0 + bcol;

    u64 acc[16][2];
    #pragma unroll
    for (int r = 0; r < 16; r++) { acc[r][0] = 0ull; acc[r][1] = 0ull; }

    float4 a00 = *(const float4*)Aptr0;
    float4 a01 = *(const float4*)(Aptr0 + 4);
    float4 a10 = *(const float4*)Aptr1;
    float4 a11 = *(const float4*)(Aptr1 + 4);
    float4 bv0 = *(const float4*)Bptr0;
    float4 bv1 = *(const float4*)Bptr1;

    As[0][ak + 0][arow] = a00.x;  As[0][ak + 1][arow] = a00.y;
    As[0][ak + 2][arow] = a00.z;  As[0][ak + 3][arow] = a00.w;
    As[0][ak + 4][arow] = a01.x;  As[0][ak + 5][arow] = a01.y;
    As[0][ak + 6][arow] = a01.z;  As[0][ak + 7][arow] = a01.w;
    As[0][ak + 0][arow + 64] = a10.x;  As[0][ak + 1][arow + 64] = a10.y;
    As[0][ak + 2][arow + 64] = a10.z;  As[0][ak + 3][arow + 64] = a10.w;
    As[0][ak + 4][arow + 64] = a11.x;  As[0][ak + 5][arow + 64] = a11.y;
    As[0][ak + 6][arow + 64] = a11.z;  As[0][ak + 7][arow + 64] = a11.w;
    *(float4*)&Bs[0][brow][bcol]     = bv0;
    *(float4*)&Bs[0][brow + 8][bcol] = bv1;
    __syncthreads();

    for (int t = 0; t < GNK; t++) {
        int buf = t & 1;
        if (t + 1 < GNK) {
            a00 = *(const float4*)(Aptr0 + (t + 1) * GBK);
            a01 = *(const float4*)(Aptr0 + (t + 1) * GBK + 4);
            a10 = *(const float4*)(Aptr1 + (t + 1) * GBK);
            a11 = *(const float4*)(Aptr1 + (t + 1) * GBK + 4);
            bv0 = *(const float4*)(Bptr0 + (size_t)(t + 1) * GBK * N);
            bv1 = *(const float4*)(Bptr1 + (size_t)(t + 1) * GBK * N);
        }

        #pragma unroll
        for (int kk = 0; kk < GBK; kk++) {
            float4 af0 = *(const float4*)&As[buf][kk][ty * 8];
            float4 af1 = *(const float4*)&As[buf][kk][ty * 8 + 4];
            float4 af2 = *(const float4*)&As[buf][kk][64 + ty * 8];
            float4 af3 = *(const float4*)&As[buf][kk][64 + ty * 8 + 4];
            ulonglong2 b01 = *(const ulonglong2*)&Bs[buf][kk][tx * 4];

            float am[16] = { af0.x, af0.y, af0.z, af0.w, af1.x, af1.y, af1.z, af1.w,
                             af2.x, af2.y, af2.z, af2.w, af3.x, af3.y, af3.z, af3.w };
            #pragma unroll
            for (int r = 0; r < 16; r++) {
                u64 ad = fdup(am[r]);
                acc[r][0] = ffma2(ad, b01.x, acc[r][0]);
                acc[r][1] = ffma2(ad, b01.y, acc[r][1]);
            }
        }

        if (t + 1 < GNK) {
            int nb = buf ^ 1;
            As[nb][ak + 0][arow] = a00.x;  As[nb][ak + 1][arow] = a00.y;
            As[nb][ak + 2][arow] = a00.z;  As[nb][ak + 3][arow] = a00.w;
            As[nb][ak + 4][arow] = a01.x;  As[nb][ak + 5][arow] = a01.y;
            As[nb][ak + 6][arow] = a01.z;  As[nb][ak + 7][arow] = a01.w;
            As[nb][ak + 0][arow + 64] = a10.x;  As[nb][ak + 1][arow + 64] = a10.y;
            As[nb][ak + 2][arow + 64] = a10.z;  As[nb][ak + 3][arow + 64] = a10.w;
            As[nb][ak + 4][arow + 64] = a11.x;  As[nb][ak + 5][arow + 64] = a11.y;
            As[nb][ak + 6][arow + 64] = a11.z;  As[nb][ak + 7][arow + 64] = a11.w;
            *(float4*)&Bs[nb][brow][bcol]     = bv0;
            *(float4*)&Bs[nb][brow + 8][bcol] = bv1;
        }
        __syncthreads();
    }

    #pragma unroll
    for (int r = 0; r < 16; r++) {
        int row = (r < 8) ? (m0 + ty * 8 + r) : (m0 + 64 + ty * 8 + (r - 8));
        float2 c0 = funpack(acc[r][0]);
        float2 c1 = funpack(acc[r][1]);
        *(float4*)&C[row * N + n0 + tx * 4] = make_float4(c0.x, c0.y, c1.x, c1.y);
    }
}

__global__ __launch_bounds__(128, 2) void gemm3_kernel(const float* __restrict__ q,
                                                       const float* __restrict__ qw,
                                                       const float* __restrict__ k,
                                                       const float* __restrict__ kw,
                                                       const float* __restrict__ v,
                                                       const float* __restrict__ vw) {
    const float* A;
    const float* B;
    float* C;
    if (blockIdx.z == 0)      { A = q; B = qw; C = g_wq; }
    else if (blockIdx.z == 1) { A = k; B = kw; C = g_wk; }
    else                      { A = v; B = vw; C = g_wv; }
    sgemm_tile(A, B, C, MDIM, MDIM);
}

__global__ __launch_bounds__(128, 2) void gemm_out_kernel(const float* __restrict__ ow,
                                                          float* __restrict__ out) {
    sgemm_tile(g_heads, ow, out, MDIM, MDIM);
}

// ---------------- pass A: per-(h,j) column stats over i, fused vt = wv/D ----------------
// Also STORES the raw dot sdot into g_s[h][i][j] (coalesced: warp spans j).
// grid: (J/128, NHEAD), block 128. Thread owns one column j of head h.
__global__ __launch_bounds__(128) void stats_kernel() {
    int h = blockIdx.y;
    int j = blockIdx.x * 128 + threadIdx.x;
    int c0 = h * HD;

    u64 kp[8];     // 16 k-values as 8 pairs
    {
        const ulonglong2* krow = (const ulonglong2*)&g_wk[j * MDIM + c0];
        #pragma unroll
        for (int k = 0; k < 4; k++) {
            ulonglong2 t = krow[k];
            kp[2 * k] = t.x; kp[2 * k + 1] = t.y;
        }
    }

    __shared__ float sq[128][20];   // 80B row stride (16B aligned)

    float m = -1e30f;
    float D = 0.0f;

    for (int i0 = 0; i0 < I_LEN; i0 += 128) {
        __syncthreads();
        {
            int t = threadIdx.x;
            const float* qrow = &g_wq[(i0 + t) * MDIM + c0];
            #pragma unroll
            for (int k = 0; k < 16; k += 4)
                *(float4*)&sq[t][k] = *(const float4*)&qrow[k];
        }
        __syncthreads();

        float* sdst = &g_s[((size_t)h * I_LEN + i0) * J_LEN + j];

        #pragma unroll 4
        for (int ii = 0; ii < 128; ii++) {
            ulonglong2 q01 = *(const ulonglong2*)&sq[ii][0];
            ulonglong2 q23 = *(const ulonglong2*)&sq[ii][4];
            ulonglong2 q45 = *(const ulonglong2*)&sq[ii][8];
            ulonglong2 q67 = *(const ulonglong2*)&sq[ii][12];
            u64 pA = 0ull, pB = 0ull;
            pA = ffma2(kp[0], q01.x, pA);  pB = ffma2(kp[1], q01.y, pB);
            pA = ffma2(kp[2], q23.x, pA);  pB = ffma2(kp[3], q23.y, pB);
            pA = ffma2(kp[4], q45.x, pA);  pB = ffma2(kp[5], q45.y, pB);
            pA = ffma2(kp[6], q67.x, pA);  pB = ffma2(kp[7], q67.y, pB);
            float2 fa = funpack(pA);
            float2 fb = funpack(pB);
            float sdot = ((fa.x + fa.y) + (fb.x + fb.y));
            sdst[(size_t)ii * J_LEN] = sdot;            // coalesced across warp (j-contig)
            float s = sdot * CSCALE;                     // log2-domain logit
            // branch-free online update; ex2(0)==1.0 exactly on the common path
            float mn = fmaxf(m, s);
            float e_old = fexp2(m - mn);
            float e_new = fexp2(s - mn);
            D = __fmaf_rn(D, e_old, e_new);
            m = mn;
        }
    }

    float invd = 1.0f / D;
    g_m[h * J_LEN + j] = m;

    // fused vtilde: vt[j,h,:] = wv[j,h,:] * invd
    {
        const float* vr  = &g_wv[j * MDIM + c0];
        float*       vtr = &g_vt[j * MDIM + c0];
        #pragma unroll
        for (int k = 0; k < 16; k += 4) {
            float4 t = *(const float4*)&vr[k];
            t.x *= invd; t.y *= invd; t.z *= invd; t.w *= invd;
            *(float4*)&vtr[k] = t;
        }
    }
}

// ---------------- pass B: heads[i,h,:] = sum_j 2^(sdot*CSCALE - m) * vt[j,h,:] ----------
// Loads sdot from g_s (no dot recompute). grid: (I/256, NHEAD), block 128;
// each thread owns 2 i-rows and streams its s-rows sequentially (L1-cached).
__global__ __launch_bounds__(128) void attn_kernel() {
    int h = blockIdx.y;
    int c0 = h * HD;
    int ia = blockIdx.x * 256 + threadIdx.x;
    int ib = ia + 128;

    const float* srow_a = &g_s[((size_t)h * I_LEN + ia) * J_LEN];
    const float* srow_b = &g_s[((size_t)h * I_LEN + ib) * J_LEN];

    u64 aa[8], ab[8];
    #pragma unroll
    for (int v = 0; v < 8; v++) { aa[v] = 0ull; ab[v] = 0ull; }

    __shared__ float sv[128][20];
    __shared__ float sm[128];

    for (int j0 = 0; j0 < J_LEN; j0 += 128) {
        __syncthreads();
        {
            int t = threadIdx.x;
            const float* vrow = &g_vt[(j0 + t) * MDIM + c0];
            #pragma unroll
            for (int k = 0; k < 16; k += 4)
                *(float4*)&sv[t][k] = *(const float4*)&vrow[k];
            sm[t] = g_m[h * J_LEN + j0 + t];
        }
        __syncthreads();

        #pragma unroll 4
        for (int jc = 0; jc < 128; jc += 4) {
            float4 s4a = *(const float4*)&srow_a[j0 + jc];
            float4 s4b = *(const float4*)&srow_b[j0 + jc];
            float sa4[4] = { s4a.x, s4a.y, s4a.z, s4a.w };
            float sb4[4] = { s4b.x, s4b.y, s4b.z, s4b.w };

            #pragma unroll
            for (int c = 0; c < 4; c++) {
                int jj = jc + c;
                float mj = sm[jj];
                float ea = fexp2(__fmaf_rn(sa4[c], CSCALE, -mj));
                float eb = fexp2(__fmaf_rn(sb4[c], CSCALE, -mj));
                u64 ed = fdup(ea);
                u64 fd = fdup(eb);

                ulonglong2 v01 = *(const ulonglong2*)&sv[jj][0];
                ulonglong2 v23 = *(const ulonglong2*)&sv[jj][4];
                ulonglong2 v45 = *(const ulonglong2*)&sv[jj][8];
                ulonglong2 v67 = *(const ulonglong2*)&sv[jj][12];
                u64 vr[8] = { v01.x, v01.y, v23.x, v23.y, v45.x, v45.y, v67.x, v67.y };
                #pragma unroll
                for (int v = 0; v < 8; v++) {
                    aa[v] = ffma2(ed, vr[v], aa[v]);
                    ab[v] = ffma2(fd, vr[v], ab[v]);
                }
            }
        }
    }

    {
        float* oa = &g_heads[ia * MDIM + c0];
        float* ob = &g_heads[ib * MDIM + c0];
        #pragma unroll
        for (int k = 0; k < 4; k++) {
            float2 p0 = funpack(aa[2 * k]);
            float2 p1 = funpack(aa[2 * k + 1]);
            *(float4*)&oa[4 * k] = make_float4(p0.x, p0.y, p1.x, p1.y);
            float2 r0 = funpack(ab[2 * k]);
            float2 r1 = funpack(ab[2 * k + 1]);
            *(float4*)&ob[4 * k] = make_float4(r0.x, r0.y, r1.x, r1.y);
        }
    }
}

// ---------------- launch ----------------
extern "C" void kernel_launch(void* const* d_in, const int* in_sizes, int n_in,
                              void* d_out, int out_size) {
    (void)in_sizes; (void)n_in; (void)out_size;
    const float* q  = (const float*)d_in[0];
    const float* k  = (const float*)d_in[1];
    const float* v  = (const float*)d_in[2];
    const float* qw = (const float*)d_in[3];
    const float* kw = (const float*)d_in[4];
    const float* vw = (const float*)d_in[5];
    const float* ow = (const float*)d_in[6];
    float* out = (float*)d_out;

    dim3 ggrid3(MDIM / GBN, I_LEN / GBM, 3);
    gemm3_kernel<<<ggrid3, 128>>>(q, qw, k, kw, v, vw);

    stats_kernel<<<dim3(J_LEN / 128, NHEAD), 128>>>();

    attn_kernel<<<dim3(I_LEN / 256, NHEAD), 128>>>();

    gemm_out_kernel<<<dim3(MDIM / GBN, I_LEN / GBM), 128>>>(ow, out);
}

// round 13
// speedup vs baseline: 1.2745x; 1.1054x over previous
#include <cuda_runtime.h>

// Problem constants
#define I_LEN 2048
#define J_LEN 2048
#define MDIM  1024
#define NHEAD 64     // "head" axis (weights dim1)
#define HD    16     // per-head contracted feature dim (weights dim2)

// combined scale: (1/sqrt(64)) * log2(e)  -- logits kept in log2 domain
#define CSCALE 0.18033688011112042f

typedef unsigned long long u64;

// ---------------- scratch (static device globals; no allocation) ----------------
__device__ float g_wq[I_LEN * MDIM];
__device__ float g_wk[J_LEN * MDIM];
__device__ float g_wv[J_LEN * MDIM];
__device__ float g_vt[J_LEN * MDIM];      // wv * invD (written by stats; idempotent)
__device__ float g_heads[I_LEN * MDIM];
__device__ float g_m[NHEAD * J_LEN];      // column max of log2-scaled logits
__device__ float g_s[(size_t)NHEAD * I_LEN * J_LEN];  // SCALED logit s[h][i][j] (1 GiB)

// ---------------- packed fp32x2 FMA (Blackwell sm_100+) ----------------
__device__ __forceinline__ u64 ffma2(u64 a, u64 b, u64 c) {
    u64 d;
    asm("fma.rn.f32x2 %0, %1, %2, %3;" : "=l"(d) : "l"(a), "l"(b), "l"(c));
    return d;
}
__device__ __forceinline__ u64 fdup(float x) {
    u64 d;
    asm("mov.b64 %0, {%1, %1};" : "=l"(d) : "f"(x));
    return d;
}
__device__ __forceinline__ float2 funpack(u64 p) {
    float2 r;
    asm("mov.b64 {%0, %1}, %2;" : "=f"(r.x), "=f"(r.y) : "l"(p));
    return r;
}

// ---------------- exp2 on the MUFU pipe ----------------
__device__ __forceinline__ float fexp2(float x) {
    float y;
    asm("ex2.approx.ftz.f32 %0, %1;" : "=f"(y) : "f"(x));
    return y;
}

// ---------------- SGEMM: C[2048x1024] = A[2048xK] @ B[Kx1024], K=1024 ----------------
// 128x64 tile (M x N), BK=16, 128 threads, 16m x 4n microtile per thread. (unchanged)
#define GBM 128
#define GBN 64
#define GBK 16
#define GNK (MDIM / GBK)

__device__ __forceinline__ void sgemm_tile(const float* __restrict__ A,
                                           const float* __restrict__ B,
                                           float* __restrict__ C,
                                           int N, int K) {
    __shared__ float As[2][GBK][GBM];   // transposed: As[k][m], 8KB per buffer
    __shared__ float Bs[2][GBK][GBN];   // 4KB per buffer

    int tid = threadIdx.x;   // 0..127
    int m0 = blockIdx.y * GBM;
    int n0 = blockIdx.x * GBN;

    int arow = tid >> 1;            // 0..63
    int ak   = (tid & 1) * 8;       // 0 or 8
    int brow = tid >> 4;            // 0..7
    int bcol = (tid & 15) * 4;      // 0..60

    int tx = tid & 15;              // n-group: cols n0 + tx*4 .. +3
    int ty = tid >> 4;              // m-group (0..7)

    const float* Aptr0 = A + (m0 + arow) * K + ak;
    const float* Aptr1 = A + (m0 + 64 + arow) * K + ak;
    const float* Bptr0 = B + brow * N + n0 + bcol;
    const float* Bptr1 = B + (brow + 8) * N + n0 + bcol;

    u64 acc[16][2];
    #pragma unroll
    for (int r = 0; r < 16; r++) { acc[r][0] = 0ull; acc[r][1] = 0ull; }

    float4 a00 = *(const float4*)Aptr0;
    float4 a01 = *(const float4*)(Aptr0 + 4);
    float4 a10 = *(const float4*)Aptr1;
    float4 a11 = *(const float4*)(Aptr1 + 4);
    float4 bv0 = *(const float4*)Bptr0;
    float4 bv1 = *(const float4*)Bptr1;

    As[0][ak + 0][arow] = a00.x;  As[0][ak + 1][arow] = a00.y;
    As[0][ak + 2][arow] = a00.z;  As[0][ak + 3][arow] = a00.w;
    As[0][ak + 4][arow] = a01.x;  As[0][ak + 5][arow] = a01.y;
    As[0][ak + 6][arow] = a01.z;  As[0][ak + 7][arow] = a01.w;
    As[0][ak + 0][arow + 64] = a10.x;  As[0][ak + 1][arow + 64] = a10.y;
    As[0][ak + 2][arow + 64] = a10.z;  As[0][ak + 3][arow + 64] = a10.w;
    As[0][ak + 4][arow + 64] = a11.x;  As[0][ak + 5][arow + 64] = a11.y;
    As[0][ak + 6][arow + 64] = a11.z;  As[0][ak + 7][arow + 64] = a11.w;
    *(float4*)&Bs[0][brow][bcol]     = bv0;
    *(float4*)&Bs[0][brow + 8][bcol] = bv1;
    __syncthreads();

    for (int t = 0; t < GNK; t++) {
        int buf = t & 1;
        if (t + 1 < GNK) {
            a00 = *(const float4*)(Aptr0 + (t + 1) * GBK);
            a01 = *(const float4*)(Aptr0 + (t + 1) * GBK + 4);
            a10 = *(const float4*)(Aptr1 + (t + 1) * GBK);
            a11 = *(const float4*)(Aptr1 + (t + 1) * GBK + 4);
            bv0 = *(const float4*)(Bptr0 + (size_t)(t + 1) * GBK * N);
            bv1 = *(const float4*)(Bptr1 + (size_t)(t + 1) * GBK * N);
        }

        #pragma unroll
        for (int kk = 0; kk < GBK; kk++) {
            float4 af0 = *(const float4*)&As[buf][kk][ty * 8];
            float4 af1 = *(const float4*)&As[buf][kk][ty * 8 + 4];
            float4 af2 = *(const float4*)&As[buf][kk][64 + ty * 8];
            float4 af3 = *(const float4*)&As[buf][kk][64 + ty * 8 + 4];
            ulonglong2 b01 = *(const ulonglong2*)&Bs[buf][kk][tx * 4];

            float am[16] = { af0.x, af0.y, af0.z, af0.w, af1.x, af1.y, af1.z, af1.w,
                             af2.x, af2.y, af2.z, af2.w, af3.x, af3.y, af3.z, af3.w };
            #pragma unroll
            for (int r = 0; r < 16; r++) {
                u64 ad = fdup(am[r]);
                acc[r][0] = ffma2(ad, b01.x, acc[r][0]);
                acc[r][1] = ffma2(ad, b01.y, acc[r][1]);
            }
        }

        if (t + 1 < GNK) {
            int nb = buf ^ 1;
            As[nb][ak + 0][arow] = a00.x;  As[nb][ak + 1][arow] = a00.y;
            As[nb][ak + 2][arow] = a00.z;  As[nb][ak + 3][arow] = a00.w;
            As[nb][ak + 4][arow] = a01.x;  As[nb][ak + 5][arow] = a01.y;
            As[nb][ak + 6][arow] = a01.z;  As[nb][ak + 7][arow] = a01.w;
            As[nb][ak + 0][arow + 64] = a10.x;  As[nb][ak + 1][arow + 64] = a10.y;
            As[nb][ak + 2][arow + 64] = a10.z;  As[nb][ak + 3][arow + 64] = a10.w;
            As[nb][ak + 4][arow + 64] = a11.x;  As[nb][ak + 5][arow + 64] = a11.y;
            As[nb][ak + 6][arow + 64] = a11.z;  As[nb][ak + 7][arow + 64] = a11.w;
            *(float4*)&Bs[nb][brow][bcol]     = bv0;
            *(float4*)&Bs[nb][brow + 8][bcol] = bv1;
        }
        __syncthreads();
    }

    #pragma unroll
    for (int r = 0; r < 16; r++) {
        int row = (r < 8) ? (m0 + ty * 8 + r) : (m0 + 64 + ty * 8 + (r - 8));
        float2 c0 = funpack(acc[r][0]);
        float2 c1 = funpack(acc[r][1]);
        *(float4*)&C[row * N + n0 + tx * 4] = make_float4(c0.x, c0.y, c1.x, c1.y);
    }
}

__global__ __launch_bounds__(128, 2) void gemm3_kernel(const float* __restrict__ q,
                                                       const float* __restrict__ qw,
                                                       const float* __restrict__ k,
                                                       const float* __restrict__ kw,
                                                       const float* __restrict__ v,
                                                       const float* __restrict__ vw) {
    const float* A;
    const float* B;
    float* C;
    if (blockIdx.z == 0)      { A = q; B = qw; C = g_wq; }
    else if (blockIdx.z == 1) { A = k; B = kw; C = g_wk; }
    else                      { A = v; B = vw; C = g_wv; }
    sgemm_tile(A, B, C, MDIM, MDIM);
}

__global__ __launch_bounds__(128, 2) void gemm_out_kernel(const float* __restrict__ ow,
                                                          float* __restrict__ out) {
    sgemm_tile(g_heads, ow, out, MDIM, MDIM);
}

// ---------------- pass A: per-(h,j) column stats over i, fused vt = wv/D ----------------
// Lane-split softmax: f32x2 lanes carry adjacent i. q tile transposed in smem
// (sq2[k][i]); k pre-scaled by CSCALE and fdup'd, so a 16-FFMA2 chain yields the
// finished log2-domain logits for 2 i at once (no horizontal reduce).
// Stores SCALED s to g_s. grid: (J/128, NHEAD), block 128.
__global__ __launch_bounds__(128) void stats_kernel() {
    int h = blockIdx.y;
    int j = blockIdx.x * 128 + threadIdx.x;
    int c0 = h * HD;

    u64 kp[16];    // fdup(k * CSCALE)
    {
        const float* krow = &g_wk[j * MDIM + c0];
        #pragma unroll
        for (int k = 0; k < 16; k += 4) {
            float4 t = *(const float4*)&krow[k];
            kp[k + 0] = fdup(t.x * CSCALE);
            kp[k + 1] = fdup(t.y * CSCALE);
            kp[k + 2] = fdup(t.z * CSCALE);
            kp[k + 3] = fdup(t.w * CSCALE);
        }
    }

    __shared__ float sq2[16][128];   // transposed: sq2[k][i-local]

    float m0 = -1e30f, m1 = -1e30f;  // lane-split online state (even/odd i)
    float D0 = 0.0f,   D1 = 0.0f;

    for (int i0 = 0; i0 < I_LEN; i0 += 128) {
        __syncthreads();
        {
            int t = threadIdx.x;
            const float* qrow = &g_wq[(i0 + t) * MDIM + c0];
            #pragma unroll
            for (int k = 0; k < 16; k += 4) {
                float4 v4 = *(const float4*)&qrow[k];
                sq2[k + 0][t] = v4.x;
                sq2[k + 1][t] = v4.y;
                sq2[k + 2][t] = v4.z;
                sq2[k + 3][t] = v4.w;
            }
        }
        __syncthreads();

        float* sdst = &g_s[((size_t)h * I_LEN + i0) * J_LEN + j];

        #pragma unroll 2
        for (int p = 0; p < 128; p += 4) {
            u64 acc0 = 0ull, acc1 = 0ull;
            #pragma unroll
            for (int k = 0; k < 16; k++) {
                ulonglong2 qq = *(const ulonglong2*)&sq2[k][p];   // i = p..p+3
                acc0 = ffma2(kp[k], qq.x, acc0);
                acc1 = ffma2(kp[k], qq.y, acc1);
            }
            float2 f = funpack(acc0);   // s[p], s[p+1]   (scaled, log2-domain)
            float2 g = funpack(acc1);   // s[p+2], s[p+3]

            sdst[(size_t)(p + 0) * J_LEN] = f.x;
            sdst[(size_t)(p + 1) * J_LEN] = f.y;
            sdst[(size_t)(p + 2) * J_LEN] = g.x;
            sdst[(size_t)(p + 3) * J_LEN] = g.y;

            // lane0 handles p, p+2 ; lane1 handles p+1, p+3
            float mn;
            mn = fmaxf(m0, f.x);  D0 = __fmaf_rn(D0, fexp2(m0 - mn), fexp2(f.x - mn));  m0 = mn;
            mn = fmaxf(m1, f.y);  D1 = __fmaf_rn(D1, fexp2(m1 - mn), fexp2(f.y - mn));  m1 = mn;
            mn = fmaxf(m0, g.x);  D0 = __fmaf_rn(D0, fexp2(m0 - mn), fexp2(g.x - mn));  m0 = mn;
            mn = fmaxf(m1, g.y);  D1 = __fmaf_rn(D1, fexp2(m1 - mn), fexp2(g.y - mn));  m1 = mn;
        }
    }

    // exact merge of the two lane-softmaxes (one exp2 arg is exactly 0)
    float m = fmaxf(m0, m1);
    float D = __fmaf_rn(D0, fexp2(m0 - m), D1 * fexp2(m1 - m));

    float invd = 1.0f / D;
    g_m[h * J_LEN + j] = m;

    // fused vtilde: vt[j,h,:] = wv[j,h,:] * invd
    {
        const float* vr  = &g_wv[j * MDIM + c0];
        float*       vtr = &g_vt[j * MDIM + c0];
        #pragma unroll
        for (int k = 0; k < 16; k += 4) {
            float4 t = *(const float4*)&vr[k];
            t.x *= invd; t.y *= invd; t.z *= invd; t.w *= invd;
            *(float4*)&vtr[k] = t;
        }
    }
}

// ---------------- pass B: heads[i,h,:] = sum_j 2^(s - m) * vt[j,h,:] ----------
// s loaded pre-scaled from g_s. 4 i-rows per thread (sv/sm LDS amortized 4x).
// grid: (I/512, NHEAD), block 128.
__global__ __launch_bounds__(128) void attn_kernel() {
    int h = blockIdx.y;
    int c0 = h * HD;
    int tid = threadIdx.x;
    int ibase = blockIdx.x * 512 + tid;

    const float* srow0 = &g_s[((size_t)h * I_LEN + ibase) * J_LEN];
    const float* srow1 = srow0 + (size_t)128 * J_LEN;
    const float* srow2 = srow0 + (size_t)256 * J_LEN;
    const float* srow3 = srow0 + (size_t)384 * J_LEN;

    u64 acc[4][8];
    #pragma unroll
    for (int r = 0; r < 4; r++)
        #pragma unroll
        for (int v = 0; v < 8; v++) acc[r][v] = 0ull;

    __shared__ float sv[128][20];
    __shared__ float sm[128];

    for (int j0 = 0; j0 < J_LEN; j0 += 128) {
        __syncthreads();
        {
            const float* vrow = &g_vt[(j0 + tid) * MDIM + c0];
            #pragma unroll
            for (int k = 0; k < 16; k += 4)
                *(float4*)&sv[tid][k] = *(const float4*)&vrow[k];
            sm[tid] = g_m[h * J_LEN + j0 + tid];
        }
        __syncthreads();

        #pragma unroll 2
        for (int jc = 0; jc < 128; jc += 4) {
            float4 s40 = *(const float4*)&srow0[j0 + jc];
            float4 s41 = *(const float4*)&srow1[j0 + jc];
            float4 s42 = *(const float4*)&srow2[j0 + jc];
            float4 s43 = *(const float4*)&srow3[j0 + jc];
            float sr0[4] = { s40.x, s40.y, s40.z, s40.w };
            float sr1[4] = { s41.x, s41.y, s41.z, s41.w };
            float sr2[4] = { s42.x, s42.y, s42.z, s42.w };
            float sr3[4] = { s43.x, s43.y, s43.z, s43.w };

            #pragma unroll
            for (int c = 0; c < 4; c++) {
                int jj = jc + c;
                float mj = sm[jj];
                u64 e0 = fdup(fexp2(sr0[c] - mj));
                u64 e1 = fdup(fexp2(sr1[c] - mj));
                u64 e2 = fdup(fexp2(sr2[c] - mj));
                u64 e3 = fdup(fexp2(sr3[c] - mj));

                ulonglong2 v01 = *(const ulonglong2*)&sv[jj][0];
                ulonglong2 v23 = *(const ulonglong2*)&sv[jj][4];
                ulonglong2 v45 = *(const ulonglong2*)&sv[jj][8];
                ulonglong2 v67 = *(const ulonglong2*)&sv[jj][12];
                u64 vr[8] = { v01.x, v01.y, v23.x, v23.y, v45.x, v45.y, v67.x, v67.y };
                #pragma unroll
                for (int v = 0; v < 8; v++) {
                    acc[0][v] = ffma2(e0, vr[v], acc[0][v]);
                    acc[1][v] = ffma2(e1, vr[v], acc[1][v]);
                    acc[2][v] = ffma2(e2, vr[v], acc[2][v]);
                    acc[3][v] = ffma2(e3, vr[v], acc[3][v]);
                }
            }
        }
    }

    #pragma unroll
    for (int r = 0; r < 4; r++) {
        float* orow = &g_heads[(ibase + r * 128) * MDIM + c0];
        #pragma unroll
        for (int k = 0; k < 4; k++) {
            float2 p0 = funpack(acc[r][2 * k]);
            float2 p1 = funpack(acc[r][2 * k + 1]);
            *(float4*)&orow[4 * k] = make_float4(p0.x, p0.y, p1.x, p1.y);
        }
    }
}

// ---------------- launch ----------------
extern "C" void kernel_launch(void* const* d_in, const int* in_sizes, int n_in,
                              void* d_out, int out_size) {
    (void)in_sizes; (void)n_in; (void)out_size;
    const float* q  = (const float*)d_in[0];
    const float* k  = (const float*)d_in[1];
    const float* v  = (const float*)d_in[2];
    const float* qw = (const float*)d_in[3];
    const float* kw = (const float*)d_in[4];
    const float* vw = (const float*)d_in[5];
    const float* ow = (const float*)d_in[6];
    float* out = (float*)d_out;

    dim3 ggrid3(MDIM / GBN, I_LEN / GBM, 3);
    gemm3_kernel<<<ggrid3, 128>>>(q, qw, k, kw, v, vw);

    stats_kernel<<<dim3(J_LEN / 128, NHEAD), 128>>>();

    attn_kernel<<<dim3(I_LEN / 512, NHEAD), 128>>>();

    gemm_out_kernel<<<dim3(MDIM / GBN, I_LEN / GBM), 128>>>(ow, out);
}

// round 14
// speedup vs baseline: 1.2868x; 1.0096x over previous
#include <cuda_runtime.h>

// Problem constants
#define I_LEN 2048
#define J_LEN 2048
#define MDIM  1024
#define NHEAD 64     // "head" axis (weights dim1)
#define HD    16     // per-head contracted feature dim (weights dim2)

// combined scale: (1/sqrt(64)) * log2(e)  -- logits kept in log2 domain
#define CSCALE 0.18033688011112042f

typedef unsigned long long u64;

// ---------------- scratch (static device globals; no allocation) ----------------
__device__ float g_wq[I_LEN * MDIM];
__device__ float g_wk[J_LEN * MDIM];
__device__ float g_wv[J_LEN * MDIM];
__device__ float g_vt[J_LEN * MDIM];      // wv * invD (written by stats; idempotent)
__device__ float g_heads[I_LEN * MDIM];
__device__ float g_m[NHEAD * J_LEN];      // column max of log2-scaled logits
__device__ float g_s[(size_t)NHEAD * I_LEN * J_LEN];  // SCALED logit s[h][i][j] (1 GiB)

// ---------------- packed fp32x2 FMA (Blackwell sm_100+) ----------------
__device__ __forceinline__ u64 ffma2(u64 a, u64 b, u64 c) {
    u64 d;
    asm("fma.rn.f32x2 %0, %1, %2, %3;" : "=l"(d) : "l"(a), "l"(b), "l"(c));
    return d;
}
__device__ __forceinline__ u64 fdup(float x) {
    u64 d;
    asm("mov.b64 %0, {%1, %1};" : "=l"(d) : "f"(x));
    return d;
}
__device__ __forceinline__ float2 funpack(u64 p) {
    float2 r;
    asm("mov.b64 {%0, %1}, %2;" : "=f"(r.x), "=f"(r.y) : "l"(p));
    return r;
}

// ---------------- exp2 on the MUFU pipe ----------------
__device__ __forceinline__ float fexp2(float x) {
    float y;
    asm("ex2.approx.ftz.f32 %0, %1;" : "=f"(y) : "f"(x));
    return y;
}

// ---------------- SGEMM: C[2048x1024] = A[2048xK] @ B[Kx1024], K=1024 ----------------
// 64x64 tile, BK=16, 128 threads, 8m x 4n microtile per thread.
// grid per GEMM = 16 x 32 = 512 blocks -> ~3.5 blocks/SM, ~14 warps/SM.
// Per kk: 3 LDS.128 (12 crossbar cyc) vs 16 FFMA2 (32 FMA cyc) -> FMA-bound.
#define GBM 64
#define GBN 64
#define GBK 16
#define GNK (MDIM / GBK)

__device__ __forceinline__ void sgemm_tile(const float* __restrict__ A,
                                           const float* __restrict__ B,
                                           float* __restrict__ C,
                                           int N, int K) {
    __shared__ float As[2][GBK][GBM];   // transposed: As[k][m], 4KB per buffer
    __shared__ float Bs[2][GBK][GBN];   // 4KB per buffer

    int tid = threadIdx.x;   // 0..127
    int m0 = blockIdx.y * GBM;
    int n0 = blockIdx.x * GBN;

    // A loads: 64 rows x 16 k = 1024 floats; 8 per thread (1 row, k-range ak..ak+7)
    int arow = tid >> 1;            // 0..63
    int ak   = (tid & 1) * 8;       // 0 or 8
    // B loads: 16 rows x 64 cols = 1024 floats; 8 per thread (rows brow, brow+8)
    int brow = tid >> 4;            // 0..7
    int bcol = (tid & 15) * 4;      // 0..60

    int tx = tid & 15;              // n-group: cols n0 + tx*4 .. +3
    int ty = tid >> 4;              // m-group (0..7): rows m0 + ty*8 .. +7

    const float* Aptr  = A + (m0 + arow) * K + ak;
    const float* Bptr0 = B + brow * N + n0 + bcol;
    const float* Bptr1 = B + (brow + 8) * N + n0 + bcol;

    u64 acc[8][2];
    #pragma unroll
    for (int r = 0; r < 8; r++) { acc[r][0] = 0ull; acc[r][1] = 0ull; }

    float4 a0  = *(const float4*)Aptr;
    float4 a1  = *(const float4*)(Aptr + 4);
    float4 bv0 = *(const float4*)Bptr0;
    float4 bv1 = *(const float4*)Bptr1;

    // store tile 0 (A transposed scalar)
    As[0][ak + 0][arow] = a0.x;  As[0][ak + 1][arow] = a0.y;
    As[0][ak + 2][arow] = a0.z;  As[0][ak + 3][arow] = a0.w;
    As[0][ak + 4][arow] = a1.x;  As[0][ak + 5][arow] = a1.y;
    As[0][ak + 6][arow] = a1.z;  As[0][ak + 7][arow] = a1.w;
    *(float4*)&Bs[0][brow][bcol]     = bv0;
    *(float4*)&Bs[0][brow + 8][bcol] = bv1;
    __syncthreads();

    for (int t = 0; t < GNK; t++) {
        int buf = t & 1;
        if (t + 1 < GNK) {
            a0  = *(const float4*)(Aptr + (t + 1) * GBK);
            a1  = *(const float4*)(Aptr + (t + 1) * GBK + 4);
            bv0 = *(const float4*)(Bptr0 + (size_t)(t + 1) * GBK * N);
            bv1 = *(const float4*)(Bptr1 + (size_t)(t + 1) * GBK * N);
        }

        #pragma unroll
        for (int kk = 0; kk < GBK; kk++) {
            float4 af0 = *(const float4*)&As[buf][kk][ty * 8];
            float4 af1 = *(const float4*)&As[buf][kk][ty * 8 + 4];
            ulonglong2 b01 = *(const ulonglong2*)&Bs[buf][kk][tx * 4];

            float am[8] = { af0.x, af0.y, af0.z, af0.w, af1.x, af1.y, af1.z, af1.w };
            #pragma unroll
            for (int r = 0; r < 8; r++) {
                u64 ad = fdup(am[r]);
                acc[r][0] = ffma2(ad, b01.x, acc[r][0]);
                acc[r][1] = ffma2(ad, b01.y, acc[r][1]);
            }
        }

        if (t + 1 < GNK) {
            int nb = buf ^ 1;
            As[nb][ak + 0][arow] = a0.x;  As[nb][ak + 1][arow] = a0.y;
            As[nb][ak + 2][arow] = a0.z;  As[nb][ak + 3][arow] = a0.w;
            As[nb][ak + 4][arow] = a1.x;  As[nb][ak + 5][arow] = a1.y;
            As[nb][ak + 6][arow] = a1.z;  As[nb][ak + 7][arow] = a1.w;
            *(float4*)&Bs[nb][brow][bcol]     = bv0;
            *(float4*)&Bs[nb][brow + 8][bcol] = bv1;
        }
        __syncthreads();
    }

    #pragma unroll
    for (int r = 0; r < 8; r++) {
        int row = m0 + ty * 8 + r;
        float2 c0 = funpack(acc[r][0]);
        float2 c1 = funpack(acc[r][1]);
        *(float4*)&C[row * N + n0 + tx * 4] = make_float4(c0.x, c0.y, c1.x, c1.y);
    }
}

__global__ __launch_bounds__(128, 3) void gemm3_kernel(const float* __restrict__ q,
                                                       const float* __restrict__ qw,
                                                       const float* __restrict__ k,
                                                       const float* __restrict__ kw,
                                                       const float* __restrict__ v,
                                                       const float* __restrict__ vw) {
    const float* A;
    const float* B;
    float* C;
    if (blockIdx.z == 0)      { A = q; B = qw; C = g_wq; }
    else if (blockIdx.z == 1) { A = k; B = kw; C = g_wk; }
    else                      { A = v; B = vw; C = g_wv; }
    sgemm_tile(A, B, C, MDIM, MDIM);
}

__global__ __launch_bounds__(128, 3) void gemm_out_kernel(const float* __restrict__ ow,
                                                          float* __restrict__ out) {
    sgemm_tile(g_heads, ow, out, MDIM, MDIM);
}

// ---------------- pass A: per-(h,j) column stats over i, fused vt = wv/D ----------------
// Lane-split softmax: f32x2 lanes carry adjacent i. q tile transposed in smem
// (sq2[k][i]); k pre-scaled by CSCALE and fdup'd, so a 16-FFMA2 chain yields the
// finished log2-domain logits for 2 i at once (no horizontal reduce).
// Stores SCALED s to g_s. grid: (J/128, NHEAD), block 128.
__global__ __launch_bounds__(128) void stats_kernel() {
    int h = blockIdx.y;
    int j = blockIdx.x * 128 + threadIdx.x;
    int c0 = h * HD;

    u64 kp[16];    // fdup(k * CSCALE)
    {
        const float* krow = &g_wk[j * MDIM + c0];
        #pragma unroll
        for (int k = 0; k < 16; k += 4) {
            float4 t = *(const float4*)&krow[k];
            kp[k + 0] = fdup(t.x * CSCALE);
            kp[k + 1] = fdup(t.y * CSCALE);
            kp[k + 2] = fdup(t.z * CSCALE);
            kp[k + 3] = fdup(t.w * CSCALE);
        }
    }

    __shared__ float sq2[16][128];   // transposed: sq2[k][i-local]

    float m0 = -1e30f, m1 = -1e30f;  // lane-split online state (even/odd i)
    float D0 = 0.0f,   D1 = 0.0f;

    for (int i0 = 0; i0 < I_LEN; i0 += 128) {
        __syncthreads();
        {
            int t = threadIdx.x;
            const float* qrow = &g_wq[(i0 + t) * MDIM + c0];
            #pragma unroll
            for (int k = 0; k < 16; k += 4) {
                float4 v4 = *(const float4*)&qrow[k];
                sq2[k + 0][t] = v4.x;
                sq2[k + 1][t] = v4.y;
                sq2[k + 2][t] = v4.z;
                sq2[k + 3][t] = v4.w;
            }
        }
        __syncthreads();

        float* sdst = &g_s[((size_t)h * I_LEN + i0) * J_LEN + j];

        #pragma unroll 2
        for (int p = 0; p < 128; p += 4) {
            u64 acc0 = 0ull, acc1 = 0ull;
            #pragma unroll
            for (int k = 0; k < 16; k++) {
                ulonglong2 qq = *(const ulonglong2*)&sq2[k][p];   // i = p..p+3
                acc0 = ffma2(kp[k], qq.x, acc0);
                acc1 = ffma2(kp[k], qq.y, acc1);
            }
            float2 f = funpack(acc0);   // s[p], s[p+1]   (scaled, log2-domain)
            float2 g = funpack(acc1);   // s[p+2], s[p+3]

            sdst[(size_t)(p + 0) * J_LEN] = f.x;
            sdst[(size_t)(p + 1) * J_LEN] = f.y;
            sdst[(size_t)(p + 2) * J_LEN] = g.x;
            sdst[(size_t)(p + 3) * J_LEN] = g.y;

            // lane0 handles p, p+2 ; lane1 handles p+1, p+3
            float mn;
            mn = fmaxf(m0, f.x);  D0 = __fmaf_rn(D0, fexp2(m0 - mn), fexp2(f.x - mn));  m0 = mn;
            mn = fmaxf(m1, f.y);  D1 = __fmaf_rn(D1, fexp2(m1 - mn), fexp2(f.y - mn));  m1 = mn;
            mn = fmaxf(m0, g.x);  D0 = __fmaf_rn(D0, fexp2(m0 - mn), fexp2(g.x - mn));  m0 = mn;
            mn = fmaxf(m1, g.y);  D1 = __fmaf_rn(D1, fexp2(m1 - mn), fexp2(g.y - mn));  m1 = mn;
        }
    }

    // exact merge of the two lane-softmaxes (one exp2 arg is exactly 0)
    float m = fmaxf(m0, m1);
    float D = __fmaf_rn(D0, fexp2(m0 - m), D1 * fexp2(m1 - m));

    float invd = 1.0f / D;
    g_m[h * J_LEN + j] = m;

    // fused vtilde: vt[j,h,:] = wv[j,h,:] * invd
    {
        const float* vr  = &g_wv[j * MDIM + c0];
        float*       vtr = &g_vt[j * MDIM + c0];
        #pragma unroll
        for (int k = 0; k < 16; k += 4) {
            float4 t = *(const float4*)&vr[k];
            t.x *= invd; t.y *= invd; t.z *= invd; t.w *= invd;
            *(float4*)&vtr[k] = t;
        }
    }
}

// ---------------- pass B: heads[i,h,:] = sum_j 2^(s - m) * vt[j,h,:] ----------
// s loaded pre-scaled from g_s. 4 i-rows per thread (sv/sm LDS amortized 4x).
// grid: (I/512, NHEAD), block 128.
__global__ __launch_bounds__(128) void attn_kernel() {
    int h = blockIdx.y;
    int c0 = h * HD;
    int tid = threadIdx.x;
    int ibase = blockIdx.x * 512 + tid;

    const float* srow0 = &g_s[((size_t)h * I_LEN + ibase) * J_LEN];
    const float* srow1 = srow0 + (size_t)128 * J_LEN;
    const float* srow2 = srow0 + (size_t)256 * J_LEN;
    const float* srow3 = srow0 + (size_t)384 * J_LEN;

    u64 acc[4][8];
    #pragma unroll
    for (int r = 0; r < 4; r++)
        #pragma unroll
        for (int v = 0; v < 8; v++) acc[r][v] = 0ull;

    __shared__ float sv[128][20];
    __shared__ float sm[128];

    for (int j0 = 0; j0 < J_LEN; j0 += 128) {
        __syncthreads();
        {
            const float* vrow = &g_vt[(j0 + tid) * MDIM + c0];
            #pragma unroll
            for (int k = 0; k < 16; k += 4)
                *(float4*)&sv[tid][k] = *(const float4*)&vrow[k];
            sm[tid] = g_m[h * J_LEN + j0 + tid];
        }
        __syncthreads();

        #pragma unroll 2
        for (int jc = 0; jc < 128; jc += 4) {
            float4 s40 = *(const float4*)&srow0[j0 + jc];
            float4 s41 = *(const float4*)&srow1[j0 + jc];
            float4 s42 = *(const float4*)&srow2[j0 + jc];
            float4 s43 = *(const float4*)&srow3[j0 + jc];
            float sr0[4] = { s40.x, s40.y, s40.z, s40.w };
            float sr1[4] = { s41.x, s41.y, s41.z, s41.w };
            float sr2[4] = { s42.x, s42.y, s42.z, s42.w };
            float sr3[4] = { s43.x, s43.y, s43.z, s43.w };

            #pragma unroll
            for (int c = 0; c < 4; c++) {
                int jj = jc + c;
                float mj = sm[jj];
                u64 e0 = fdup(fexp2(sr0[c] - mj));
                u64 e1 = fdup(fexp2(sr1[c] - mj));
                u64 e2 = fdup(fexp2(sr2[c] - mj));
                u64 e3 = fdup(fexp2(sr3[c] - mj));

                ulonglong2 v01 = *(const ulonglong2*)&sv[jj][0];
                ulonglong2 v23 = *(const ulonglong2*)&sv[jj][4];
                ulonglong2 v45 = *(const ulonglong2*)&sv[jj][8];
                ulonglong2 v67 = *(const ulonglong2*)&sv[jj][12];
                u64 vr[8] = { v01.x, v01.y, v23.x, v23.y, v45.x, v45.y, v67.x, v67.y };
                #pragma unroll
                for (int v = 0; v < 8; v++) {
                    acc[0][v] = ffma2(e0, vr[v], acc[0][v]);
                    acc[1][v] = ffma2(e1, vr[v], acc[1][v]);
                    acc[2][v] = ffma2(e2, vr[v], acc[2][v]);
                    acc[3][v] = ffma2(e3, vr[v], acc[3][v]);
                }
            }
        }
    }

    #pragma unroll
    for (int r = 0; r < 4; r++) {
        float* orow = &g_heads[(ibase + r * 128) * MDIM + c0];
        #pragma unroll
        for (int k = 0; k < 4; k++) {
            float2 p0 = funpack(acc[r][2 * k]);
            float2 p1 = funpack(acc[r][2 * k + 1]);
            *(float4*)&orow[4 * k] = make_float4(p0.x, p0.y, p1.x, p1.y);
        }
    }
}

// ---------------- launch ----------------
extern "C" void kernel_launch(void* const* d_in, const int* in_sizes, int n_in,
                              void* d_out, int out_size) {
    (void)in_sizes; (void)n_in; (void)out_size;
    const float* q  = (const float*)d_in[0];
    const float* k  = (const float*)d_in[1];
    const float* v  = (const float*)d_in[2];
    const float* qw = (const float*)d_in[3];
    const float* kw = (const float*)d_in[4];
    const float* vw = (const float*)d_in[5];
    const float* ow = (const float*)d_in[6];
    float* out = (float*)d_out;

    dim3 ggrid3(MDIM / GBN, I_LEN / GBM, 3);
    gemm3_kernel<<<ggrid3, 128>>>(q, qw, k, kw, v, vw);

    stats_kernel<<<dim3(J_LEN / 128, NHEAD), 128>>>();

    attn_kernel<<<dim3(I_LEN / 512, NHEAD), 128>>>();

    gemm_out_kernel<<<dim3(MDIM / GBN, I_LEN / GBM), 128>>>(ow, out);
}

// round 15
// speedup vs baseline: 1.2929x; 1.0048x over previous
#include <cuda_runtime.h>

// Problem constants
#define I_LEN 2048
#define J_LEN 2048
#define MDIM  1024
#define NHEAD 64     // "head" axis (weights dim1)
#define HD    16     // per-head contracted feature dim (weights dim2)

// combined scale: (1/sqrt(64)) * log2(e)  -- logits kept in log2 domain
#define CSCALE 0.18033688011112042f

typedef unsigned long long u64;

// ---------------- scratch (static device globals; no allocation) ----------------
__device__ float g_wq[I_LEN * MDIM];
__device__ float g_wk[J_LEN * MDIM];
__device__ float g_wv[J_LEN * MDIM];
__device__ float g_vt[J_LEN * MDIM];      // wv * invD (written by stats; idempotent)
__device__ float g_heads[I_LEN * MDIM];
__device__ float g_m[NHEAD * J_LEN];      // column max of log2-scaled logits
__device__ float g_s[(size_t)NHEAD * I_LEN * J_LEN];  // SCALED logit s[h][i][j] (1 GiB)
__device__ float g_p0[I_LEN * MDIM];      // gemm_out split-K partial (k 0..511)
__device__ float g_p1[I_LEN * MDIM];      // gemm_out split-K partial (k 512..1023)

// ---------------- packed fp32x2 FMA (Blackwell sm_100+) ----------------
__device__ __forceinline__ u64 ffma2(u64 a, u64 b, u64 c) {
    u64 d;
    asm("fma.rn.f32x2 %0, %1, %2, %3;" : "=l"(d) : "l"(a), "l"(b), "l"(c));
    return d;
}
__device__ __forceinline__ u64 fdup(float x) {
    u64 d;
    asm("mov.b64 %0, {%1, %1};" : "=l"(d) : "f"(x));
    return d;
}
__device__ __forceinline__ float2 funpack(u64 p) {
    float2 r;
    asm("mov.b64 {%0, %1}, %2;" : "=f"(r.x), "=f"(r.y) : "l"(p));
    return r;
}

// ---------------- exp2 on the MUFU pipe ----------------
__device__ __forceinline__ float fexp2(float x) {
    float y;
    asm("ex2.approx.ftz.f32 %0, %1;" : "=f"(y) : "f"(x));
    return y;
}

// ---------------- SGEMM tile: 128x128, BK=16, 128 threads, 16m x 8n microtile ------
// Crossbar:FMA per kk per SM = 24 cyc : 32 cyc = 0.75 -> FMA-bound (the only
// feasible ratio<1 config). Grid parallelism supplied by z (3 GEMMs / split-K).
#define GBM 128
#define GBN 128
#define GBK 16

__device__ __forceinline__ void sgemm_tile_k(const float* __restrict__ A,
                                             const float* __restrict__ B,
                                             float* __restrict__ C,
                                             int N, int K,
                                             int k_begin, int n_ktiles) {
    __shared__ float As[2][GBK][GBM];   // transposed: As[k][m], 8KB per buffer
    __shared__ float Bs[2][GBK][GBN];   // 8KB per buffer

    int tid = threadIdx.x;   // 0..127
    int m0 = blockIdx.y * GBM;
    int n0 = blockIdx.x * GBN;

    // A loads: 128 rows x 16 k; rows arow, arow+64; k-range ak..ak+7
    int arow = tid >> 1;            // 0..63
    int ak   = (tid & 1) * 8;       // 0 or 8
    // B loads: 16 rows x 128 cols; rows brow, +4, +8, +12
    int brow = tid >> 5;            // 0..3
    int bcol = (tid & 31) * 4;      // 0..124

    int tx = tid & 15;              // n-group: cols n0 + tx*8 .. +7
    int ty = tid >> 4;              // m-group: rows ty*8..+7 and 64+ty*8..+7

    const float* Aptr0 = A + (m0 + arow) * K + k_begin + ak;
    const float* Aptr1 = A + (m0 + 64 + arow) * K + k_begin + ak;
    const float* Bptr0 = B + (size_t)(k_begin + brow) * N + n0 + bcol;
    const float* Bptr1 = B + (size_t)(k_begin + brow + 4) * N + n0 + bcol;
    const float* Bptr2 = B + (size_t)(k_begin + brow + 8) * N + n0 + bcol;
    const float* Bptr3 = B + (size_t)(k_begin + brow + 12) * N + n0 + bcol;

    u64 acc[16][4];
    #pragma unroll
    for (int r = 0; r < 16; r++)
        #pragma unroll
        for (int c = 0; c < 4; c++) acc[r][c] = 0ull;

    float4 a00 = *(const float4*)Aptr0;
    float4 a01 = *(const float4*)(Aptr0 + 4);
    float4 a10 = *(const float4*)Aptr1;
    float4 a11 = *(const float4*)(Aptr1 + 4);
    float4 bv0 = *(const float4*)Bptr0;
    float4 bv1 = *(const float4*)Bptr1;
    float4 bv2 = *(const float4*)Bptr2;
    float4 bv3 = *(const float4*)Bptr3;

    As[0][ak + 0][arow] = a00.x;  As[0][ak + 1][arow] = a00.y;
    As[0][ak + 2][arow] = a00.z;  As[0][ak + 3][arow] = a00.w;
    As[0][ak + 4][arow] = a01.x;  As[0][ak + 5][arow] = a01.y;
    As[0][ak + 6][arow] = a01.z;  As[0][ak + 7][arow] = a01.w;
    As[0][ak + 0][arow + 64] = a10.x;  As[0][ak + 1][arow + 64] = a10.y;
    As[0][ak + 2][arow + 64] = a10.z;  As[0][ak + 3][arow + 64] = a10.w;
    As[0][ak + 4][arow + 64] = a11.x;  As[0][ak + 5][arow + 64] = a11.y;
    As[0][ak + 6][arow + 64] = a11.z;  As[0][ak + 7][arow + 64] = a11.w;
    *(float4*)&Bs[0][brow][bcol]      = bv0;
    *(float4*)&Bs[0][brow + 4][bcol]  = bv1;
    *(float4*)&Bs[0][brow + 8][bcol]  = bv2;
    *(float4*)&Bs[0][brow + 12][bcol] = bv3;
    __syncthreads();

    for (int t = 0; t < n_ktiles; t++) {
        int buf = t & 1;
        if (t + 1 < n_ktiles) {
            a00 = *(const float4*)(Aptr0 + (t + 1) * GBK);
            a01 = *(const float4*)(Aptr0 + (t + 1) * GBK + 4);
            a10 = *(const float4*)(Aptr1 + (t + 1) * GBK);
            a11 = *(const float4*)(Aptr1 + (t + 1) * GBK + 4);
            bv0 = *(const float4*)(Bptr0 + (size_t)(t + 1) * GBK * N);
            bv1 = *(const float4*)(Bptr1 + (size_t)(t + 1) * GBK * N);
            bv2 = *(const float4*)(Bptr2 + (size_t)(t + 1) * GBK * N);
            bv3 = *(const float4*)(Bptr3 + (size_t)(t + 1) * GBK * N);
        }

        #pragma unroll
        for (int kk = 0; kk < GBK; kk++) {
            float4 af0 = *(const float4*)&As[buf][kk][ty * 8];
            float4 af1 = *(const float4*)&As[buf][kk][ty * 8 + 4];
            float4 af2 = *(const float4*)&As[buf][kk][64 + ty * 8];
            float4 af3 = *(const float4*)&As[buf][kk][64 + ty * 8 + 4];
            ulonglong2 b01 = *(const ulonglong2*)&Bs[buf][kk][tx * 8];
            ulonglong2 b23 = *(const ulonglong2*)&Bs[buf][kk][tx * 8 + 4];

            float am[16] = { af0.x, af0.y, af0.z, af0.w, af1.x, af1.y, af1.z, af1.w,
                             af2.x, af2.y, af2.z, af2.w, af3.x, af3.y, af3.z, af3.w };
            #pragma unroll
            for (int r = 0; r < 16; r++) {
                u64 ad = fdup(am[r]);
                acc[r][0] = ffma2(ad, b01.x, acc[r][0]);
                acc[r][1] = ffma2(ad, b01.y, acc[r][1]);
                acc[r][2] = ffma2(ad, b23.x, acc[r][2]);
                acc[r][3] = ffma2(ad, b23.y, acc[r][3]);
            }
        }

        if (t + 1 < n_ktiles) {
            int nb = buf ^ 1;
            As[nb][ak + 0][arow] = a00.x;  As[nb][ak + 1][arow] = a00.y;
            As[nb][ak + 2][arow] = a00.z;  As[nb][ak + 3][arow] = a00.w;
            As[nb][ak + 4][arow] = a01.x;  As[nb][ak + 5][arow] = a01.y;
            As[nb][ak + 6][arow] = a01.z;  As[nb][ak + 7][arow] = a01.w;
            As[nb][ak + 0][arow + 64] = a10.x;  As[nb][ak + 1][arow + 64] = a10.y;
            As[nb][ak + 2][arow + 64] = a10.z;  As[nb][ak + 3][arow + 64] = a10.w;
            As[nb][ak + 4][arow + 64] = a11.x;  As[nb][ak + 5][arow + 64] = a11.y;
            As[nb][ak + 6][arow + 64] = a11.z;  As[nb][ak + 7][arow + 64] = a11.w;
            *(float4*)&Bs[nb][brow][bcol]      = bv0;
            *(float4*)&Bs[nb][brow + 4][bcol]  = bv1;
            *(float4*)&Bs[nb][brow + 8][bcol]  = bv2;
            *(float4*)&Bs[nb][brow + 12][bcol] = bv3;
        }
        __syncthreads();
    }

    #pragma unroll
    for (int r = 0; r < 16; r++) {
        int row = (r < 8) ? (m0 + ty * 8 + r) : (m0 + 64 + ty * 8 + (r - 8));
        float2 c0 = funpack(acc[r][0]);
        float2 c1 = funpack(acc[r][1]);
        float2 c2 = funpack(acc[r][2]);
        float2 c3 = funpack(acc[r][3]);
        *(float4*)&C[row * N + n0 + tx * 8]     = make_float4(c0.x, c0.y, c1.x, c1.y);
        *(float4*)&C[row * N + n0 + tx * 8 + 4] = make_float4(c2.x, c2.y, c3.x, c3.y);
    }
}

// Three projection GEMMs: grid (8, 16, 3) = 384 blocks
__global__ __launch_bounds__(128) void gemm3_kernel(const float* __restrict__ q,
                                                    const float* __restrict__ qw,
                                                    const float* __restrict__ k,
                                                    const float* __restrict__ kw,
                                                    const float* __restrict__ v,
                                                    const float* __restrict__ vw) {
    const float* A;
    const float* B;
    float* C;
    if (blockIdx.z == 0)      { A = q; B = qw; C = g_wq; }
    else if (blockIdx.z == 1) { A = k; B = kw; C = g_wk; }
    else                      { A = v; B = vw; C = g_wv; }
    sgemm_tile_k(A, B, C, MDIM, MDIM, 0, MDIM / GBK);
}

// gemm_out split-K: grid (8, 16, 2) = 256 blocks; z selects K-half and buffer
__global__ __launch_bounds__(128) void gemm_out_part_kernel(const float* __restrict__ ow) {
    float* C = (blockIdx.z == 0) ? g_p0 : g_p1;
    int k_begin = blockIdx.z * (MDIM / 2);
    sgemm_tile_k(g_heads, ow, C, MDIM, MDIM, k_begin, MDIM / (2 * GBK));
}

// merge: out = p0 + p1 (deterministic split-K reduction)
__global__ __launch_bounds__(256) void merge_kernel(float* __restrict__ out) {
    int idx = (blockIdx.x * 256 + threadIdx.x) * 4;
    float4 a = *(const float4*)&g_p0[idx];
    float4 b = *(const float4*)&g_p1[idx];
    *(float4*)&out[idx] = make_float4(a.x + b.x, a.y + b.y, a.z + b.z, a.w + b.w);
}

// ---------------- pass A: per-(h,j) column stats over i, fused vt = wv/D ----------------
// Lane-split softmax (unchanged from round 13/14).
__global__ __launch_bounds__(128) void stats_kernel() {
    int h = blockIdx.y;
    int j = blockIdx.x * 128 + threadIdx.x;
    int c0 = h * HD;

    u64 kp[16];    // fdup(k * CSCALE)
    {
        const float* krow = &g_wk[j * MDIM + c0];
        #pragma unroll
        for (int k = 0; k < 16; k += 4) {
            float4 t = *(const float4*)&krow[k];
            kp[k + 0] = fdup(t.x * CSCALE);
            kp[k + 1] = fdup(t.y * CSCALE);
            kp[k + 2] = fdup(t.z * CSCALE);
            kp[k + 3] = fdup(t.w * CSCALE);
        }
    }

    __shared__ float sq2[16][128];   // transposed: sq2[k][i-local]

    float m0 = -1e30f, m1 = -1e30f;  // lane-split online state (even/odd i)
    float D0 = 0.0f,   D1 = 0.0f;

    for (int i0 = 0; i0 < I_LEN; i0 += 128) {
        __syncthreads();
        {
            int t = threadIdx.x;
            const float* qrow = &g_wq[(i0 + t) * MDIM + c0];
            #pragma unroll
            for (int k = 0; k < 16; k += 4) {
                float4 v4 = *(const float4*)&qrow[k];
                sq2[k + 0][t] = v4.x;
                sq2[k + 1][t] = v4.y;
                sq2[k + 2][t] = v4.z;
                sq2[k + 3][t] = v4.w;
            }
        }
        __syncthreads();

        float* sdst = &g_s[((size_t)h * I_LEN + i0) * J_LEN + j];

        #pragma unroll 2
        for (int p = 0; p < 128; p += 4) {
            u64 acc0 = 0ull, acc1 = 0ull;
            #pragma unroll
            for (int k = 0; k < 16; k++) {
                ulonglong2 qq = *(const ulonglong2*)&sq2[k][p];   // i = p..p+3
                acc0 = ffma2(kp[k], qq.x, acc0);
                acc1 = ffma2(kp[k], qq.y, acc1);
            }
            float2 f = funpack(acc0);   // s[p], s[p+1]   (scaled, log2-domain)
            float2 g = funpack(acc1);   // s[p+2], s[p+3]

            sdst[(size_t)(p + 0) * J_LEN] = f.x;
            sdst[(size_t)(p + 1) * J_LEN] = f.y;
            sdst[(size_t)(p + 2) * J_LEN] = g.x;
            sdst[(size_t)(p + 3) * J_LEN] = g.y;

            float mn;
            mn = fmaxf(m0, f.x);  D0 = __fmaf_rn(D0, fexp2(m0 - mn), fexp2(f.x - mn));  m0 = mn;
            mn = fmaxf(m1, f.y);  D1 = __fmaf_rn(D1, fexp2(m1 - mn), fexp2(f.y - mn));  m1 = mn;
            mn = fmaxf(m0, g.x);  D0 = __fmaf_rn(D0, fexp2(m0 - mn), fexp2(g.x - mn));  m0 = mn;
            mn = fmaxf(m1, g.y);  D1 = __fmaf_rn(D1, fexp2(m1 - mn), fexp2(g.y - mn));  m1 = mn;
        }
    }

    float m = fmaxf(m0, m1);
    float D = __fmaf_rn(D0, fexp2(m0 - m), D1 * fexp2(m1 - m));

    float invd = 1.0f / D;
    g_m[h * J_LEN + j] = m;

    {
        const float* vr  = &g_wv[j * MDIM + c0];
        float*       vtr = &g_vt[j * MDIM + c0];
        #pragma unroll
        for (int k = 0; k < 16; k += 4) {
            float4 t = *(const float4*)&vr[k];
            t.x *= invd; t.y *= invd; t.z *= invd; t.w *= invd;
            *(float4*)&vtr[k] = t;
        }
    }
}

// ---------------- pass B: heads[i,h,:] = sum_j 2^(s - m) * vt[j,h,:] ----------
// (unchanged from round 13/14)
__global__ __launch_bounds__(128) void attn_kernel() {
    int h = blockIdx.y;
    int c0 = h * HD;
    int tid = threadIdx.x;
    int ibase = blockIdx.x * 512 + tid;

    const float* srow0 = &g_s[((size_t)h * I_LEN + ibase) * J_LEN];
    const float* srow1 = srow0 + (size_t)128 * J_LEN;
    const float* srow2 = srow0 + (size_t)256 * J_LEN;
    const float* srow3 = srow0 + (size_t)384 * J_LEN;

    u64 acc[4][8];
    #pragma unroll
    for (int r = 0; r < 4; r++)
        #pragma unroll
        for (int v = 0; v < 8; v++) acc[r][v] = 0ull;

    __shared__ float sv[128][20];
    __shared__ float sm[128];

    for (int j0 = 0; j0 < J_LEN; j0 += 128) {
        __syncthreads();
        {
            const float* vrow = &g_vt[(j0 + tid) * MDIM + c0];
            #pragma unroll
            for (int k = 0; k < 16; k += 4)
                *(float4*)&sv[tid][k] = *(const float4*)&vrow[k];
            sm[tid] = g_m[h * J_LEN + j0 + tid];
        }
        __syncthreads();

        #pragma unroll 2
        for (int jc = 0; jc < 128; jc += 4) {
            float4 s40 = *(const float4*)&srow0[j0 + jc];
            float4 s41 = *(const float4*)&srow1[j0 + jc];
            float4 s42 = *(const float4*)&srow2[j0 + jc];
            float4 s43 = *(const float4*)&srow3[j0 + jc];
            float sr0[4] = { s40.x, s40.y, s40.z, s40.w };
            float sr1[4] = { s41.x, s41.y, s41.z, s41.w };
            float sr2[4] = { s42.x, s42.y, s42.z, s42.w };
            float sr3[4] = { s43.x, s43.y, s43.z, s43.w };

            #pragma unroll
            for (int c = 0; c < 4; c++) {
                int jj = jc + c;
                float mj = sm[jj];
                u64 e0 = fdup(fexp2(sr0[c] - mj));
                u64 e1 = fdup(fexp2(sr1[c] - mj));
                u64 e2 = fdup(fexp2(sr2[c] - mj));
                u64 e3 = fdup(fexp2(sr3[c] - mj));

                ulonglong2 v01 = *(const ulonglong2*)&sv[jj][0];
                ulonglong2 v23 = *(const ulonglong2*)&sv[jj][4];
                ulonglong2 v45 = *(const ulonglong2*)&sv[jj][8];
                ulonglong2 v67 = *(const ulonglong2*)&sv[jj][12];
                u64 vr[8] = { v01.x, v01.y, v23.x, v23.y, v45.x, v45.y, v67.x, v67.y };
                #pragma unroll
                for (int v = 0; v < 8; v++) {
                    acc[0][v] = ffma2(e0, vr[v], acc[0][v]);
                    acc[1][v] = ffma2(e1, vr[v], acc[1][v]);
                    acc[2][v] = ffma2(e2, vr[v], acc[2][v]);
                    acc[3][v] = ffma2(e3, vr[v], acc[3][v]);
                }
            }
        }
    }

    #pragma unroll
    for (int r = 0; r < 4; r++) {
        float* orow = &g_heads[(ibase + r * 128) * MDIM + c0];
        #pragma unroll
        for (int k = 0; k < 4; k++) {
            float2 p0 = funpack(acc[r][2 * k]);
            float2 p1 = funpack(acc[r][2 * k + 1]);
            *(float4*)&orow[4 * k] = make_float4(p0.x, p0.y, p1.x, p1.y);
        }
    }
}

// ---------------- launch ----------------
extern "C" void kernel_launch(void* const* d_in, const int* in_sizes, int n_in,
                              void* d_out, int out_size) {
    (void)in_sizes; (void)n_in; (void)out_size;
    const float* q  = (const float*)d_in[0];
    const float* k  = (const float*)d_in[1];
    const float* v  = (const float*)d_in[2];
    const float* qw = (const float*)d_in[3];
    const float* kw = (const float*)d_in[4];
    const float* vw = (const float*)d_in[5];
    const float* ow = (const float*)d_in[6];
    float* out = (float*)d_out;

    dim3 ggrid3(MDIM / GBN, I_LEN / GBM, 3);        // 8 x 16 x 3 = 384 blocks
    gemm3_kernel<<<ggrid3, 128>>>(q, qw, k, kw, v, vw);

    stats_kernel<<<dim3(J_LEN / 128, NHEAD), 128>>>();

    attn_kernel<<<dim3(I_LEN / 512, NHEAD), 128>>>();

    dim3 ggout(MDIM / GBN, I_LEN / GBM, 2);          // 8 x 16 x 2 = 256 blocks
    gemm_out_part_kernel<<<ggout, 128>>>(ow);

    merge_kernel<<<(I_LEN * MDIM) / (256 * 4), 256>>>(out);
}